// round 1
// baseline (speedup 1.0000x reference)
#include <cuda_runtime.h>
#include <math.h>

// Problem constants
#define BB 4
#define TT 2048
#define EE 1024
#define HH 16
#define HDD 64
#define MM (BB*TT)          // 8192 rows

// ---------------- scratch (device globals; no runtime allocation) -------------
__device__ float g_q[BB*HH*TT*HDD];     // (b,h,t,d)
__device__ float g_k[BB*HH*TT*HDD];
__device__ float g_v[BB*HH*TT*HDD];
__device__ float g_att[MM*EE];          // (b,t, h*HD+d)  -- concat heads

// ---------------- QKV projection: out[(b,h,t,d)] = x[b,t,:] @ W[h][:,d] -------
// SGEMM 64x64 tile, BK=16, 256 threads, 4x4 micro-tile.
__global__ __launch_bounds__(256)
void proj_kernel(const float* __restrict__ x, const float* __restrict__ W,
                 float* __restrict__ out)
{
    __shared__ float As[16][64];   // [k][m]
    __shared__ float Bs[16][64];   // [k][n]

    const int h  = blockIdx.y;
    const int m0 = blockIdx.x * 64;
    const int tid = threadIdx.x;
    const int ty = tid >> 4, tx = tid & 15;
    const int r0 = ty * 4, c0 = tx * 4;

    const int arow = tid >> 2;          // 0..63
    const int ak4  = (tid & 3) * 4;     // 0,4,8,12
    const float* Wh = W + (size_t)h * EE * HDD;

    float acc[4][4] = {};

    for (int k0 = 0; k0 < EE; k0 += 16) {
        // A tile: 64 rows x 16 k, transposed into As[k][m]
        float4 a4 = *(const float4*)(x + (size_t)(m0 + arow) * EE + k0 + ak4);
        As[ak4+0][arow] = a4.x; As[ak4+1][arow] = a4.y;
        As[ak4+2][arow] = a4.z; As[ak4+3][arow] = a4.w;
        // B tile: W rows k0+ty, cols tx*4.. (row-major 1024x64 panel)
        *(float4*)&Bs[ty][tx*4] = *(const float4*)(Wh + (size_t)(k0 + ty) * HDD + tx*4);
        __syncthreads();

        #pragma unroll
        for (int kk = 0; kk < 16; kk++) {
            float4 a = *(float4*)&As[kk][r0];
            float4 b = *(float4*)&Bs[kk][c0];
            float av[4] = {a.x,a.y,a.z,a.w};
            float bv[4] = {b.x,b.y,b.z,b.w};
            #pragma unroll
            for (int i = 0; i < 4; i++)
                #pragma unroll
                for (int j = 0; j < 4; j++)
                    acc[i][j] += av[i] * bv[j];
        }
        __syncthreads();
    }

    #pragma unroll
    for (int i = 0; i < 4; i++) {
        int m = m0 + r0 + i;
        int b = m / TT, t = m % TT;
        float4 val = make_float4(acc[i][0], acc[i][1], acc[i][2], acc[i][3]);
        *(float4*)(out + ((size_t)(b * HH + h) * TT + t) * HDD + c0) = val;
    }
}

// ---------------- fp32 flash attention (causal), one CTA per (bh, q-tile) ----
__global__ __launch_bounds__(256)
void attn_kernel(const float* __restrict__ q, const float* __restrict__ k,
                 const float* __restrict__ v, float* __restrict__ att)
{
    extern __shared__ float sm[];
    float (*Qs)[65] = (float(*)[65])(sm);             // [r][d]
    float (*Ks)[65] = (float(*)[65])(sm + 64*65);     // [s][d]
    float (*Vs)[65] = (float(*)[65])(sm + 2*64*65);   // [s][d]
    float (*Ps)[65] = (float(*)[65])(sm + 3*64*65);   // [r][s]

    const int qi = blockIdx.x;
    const int bh = blockIdx.y;
    const size_t base = (size_t)bh * TT * HDD;

    const int tid = threadIdx.x;
    const int ty = tid >> 4, tx = tid & 15;
    const int r0 = ty * 4, c0 = tx * 4;

    const int rr = tid >> 4;            // 0..15
    const int d4 = (tid & 15) * 4;

    // load Q tile (rows qi*64 .. +63)
    #pragma unroll
    for (int p = 0; p < 4; p++) {
        int row = p * 16 + rr;
        float4 qv = *(const float4*)(q + base + (size_t)(qi*64 + row) * HDD + d4);
        Qs[row][d4+0] = qv.x; Qs[row][d4+1] = qv.y;
        Qs[row][d4+2] = qv.z; Qs[row][d4+3] = qv.w;
    }

    float mstat[4], lstat[4], o[4][4];
    #pragma unroll
    for (int i = 0; i < 4; i++) {
        mstat[i] = -1e30f; lstat[i] = 0.f;
        #pragma unroll
        for (int j = 0; j < 4; j++) o[i][j] = 0.f;
    }
    const float scale = 0.125f;   // 1/sqrt(64)

    for (int j = 0; j <= qi; j++) {
        __syncthreads();   // protect Ks/Vs/Ps from previous iteration readers
        #pragma unroll
        for (int p = 0; p < 4; p++) {
            int row = p * 16 + rr;
            float4 kv = *(const float4*)(k + base + (size_t)(j*64 + row) * HDD + d4);
            Ks[row][d4+0] = kv.x; Ks[row][d4+1] = kv.y;
            Ks[row][d4+2] = kv.z; Ks[row][d4+3] = kv.w;
            float4 vv = *(const float4*)(v + base + (size_t)(j*64 + row) * HDD + d4);
            Vs[row][d4+0] = vv.x; Vs[row][d4+1] = vv.y;
            Vs[row][d4+2] = vv.z; Vs[row][d4+3] = vv.w;
        }
        __syncthreads();

        // S = Q K^T   (4x4 per thread)
        float s[4][4] = {};
        #pragma unroll 8
        for (int kd = 0; kd < 64; kd++) {
            float qreg[4], kreg[4];
            #pragma unroll
            for (int i = 0; i < 4; i++) qreg[i] = Qs[r0+i][kd];   // broadcast
            #pragma unroll
            for (int i = 0; i < 4; i++) kreg[i] = Ks[c0+i][kd];   // pad-65: conflict-free
            #pragma unroll
            for (int i = 0; i < 4; i++)
                #pragma unroll
                for (int jj = 0; jj < 4; jj++)
                    s[i][jj] += qreg[i] * kreg[jj];
        }

        // scale + causal mask (only diagonal tile is partially masked)
        #pragma unroll
        for (int i = 0; i < 4; i++)
            #pragma unroll
            for (int jj = 0; jj < 4; jj++) {
                float sv = s[i][jj] * scale;
                if (j == qi && (c0 + jj) > (r0 + i)) sv = -1e30f;
                s[i][jj] = sv;
            }

        // online softmax update
        #pragma unroll
        for (int i = 0; i < 4; i++) {
            float rm = fmaxf(fmaxf(s[i][0], s[i][1]), fmaxf(s[i][2], s[i][3]));
            #pragma unroll
            for (int off = 8; off > 0; off >>= 1)
                rm = fmaxf(rm, __shfl_xor_sync(0xffffffffu, rm, off, 16));
            float newm = fmaxf(mstat[i], rm);
            float corr = __expf(mstat[i] - newm);
            float rs = 0.f;
            #pragma unroll
            for (int jj = 0; jj < 4; jj++) {
                float p = __expf(s[i][jj] - newm);
                s[i][jj] = p;
                rs += p;
            }
            #pragma unroll
            for (int off = 8; off > 0; off >>= 1)
                rs += __shfl_xor_sync(0xffffffffu, rs, off, 16);
            lstat[i] = lstat[i] * corr + rs;
            mstat[i] = newm;
            #pragma unroll
            for (int jj = 0; jj < 4; jj++) o[i][jj] *= corr;
        }

        // stage P
        #pragma unroll
        for (int i = 0; i < 4; i++)
            #pragma unroll
            for (int jj = 0; jj < 4; jj++)
                Ps[r0+i][c0+jj] = s[i][jj];
        __syncthreads();

        // O += P @ V
        #pragma unroll 8
        for (int ss = 0; ss < 64; ss++) {
            float pr[4], vv[4];
            #pragma unroll
            for (int i = 0; i < 4; i++) pr[i] = Ps[r0+i][ss];     // broadcast
            #pragma unroll
            for (int jj = 0; jj < 4; jj++) vv[jj] = Vs[ss][c0+jj];
            #pragma unroll
            for (int i = 0; i < 4; i++)
                #pragma unroll
                for (int jj = 0; jj < 4; jj++)
                    o[i][jj] += pr[i] * vv[jj];
        }
    }

    // epilogue: normalize + write concat-head layout
    const int b = bh / HH, h = bh % HH;
    #pragma unroll
    for (int i = 0; i < 4; i++) {
        float inv = 1.f / lstat[i];
        int t = qi * 64 + r0 + i;
        float4 val = make_float4(o[i][0]*inv, o[i][1]*inv, o[i][2]*inv, o[i][3]*inv);
        *(float4*)(att + ((size_t)(b * TT + t)) * EE + h * HDD + c0) = val;
    }
}

// ---------------- output projection: out = att @ Wo^T + bo --------------------
__global__ __launch_bounds__(256)
void oproj_kernel(const float* __restrict__ A, const float* __restrict__ Wo,
                  const float* __restrict__ bo, float* __restrict__ out)
{
    __shared__ float As[16][64];   // [k][m]
    __shared__ float Bs[16][64];   // [k][n]

    const int n0 = blockIdx.y * 64;
    const int m0 = blockIdx.x * 64;
    const int tid = threadIdx.x;
    const int ty = tid >> 4, tx = tid & 15;
    const int r0 = ty * 4, c0 = tx * 4;

    const int arow = tid >> 2;
    const int ak4  = (tid & 3) * 4;

    float acc[4][4] = {};

    for (int k0 = 0; k0 < EE; k0 += 16) {
        float4 a4 = *(const float4*)(A + (size_t)(m0 + arow) * EE + k0 + ak4);
        As[ak4+0][arow] = a4.x; As[ak4+1][arow] = a4.y;
        As[ak4+2][arow] = a4.z; As[ak4+3][arow] = a4.w;
        // B[k][n] = Wo[(n0+n)*E + k0+k] : Wo row n is k-contiguous
        float4 b4 = *(const float4*)(Wo + (size_t)(n0 + arow) * EE + k0 + ak4);
        Bs[ak4+0][arow] = b4.x; Bs[ak4+1][arow] = b4.y;
        Bs[ak4+2][arow] = b4.z; Bs[ak4+3][arow] = b4.w;
        __syncthreads();

        #pragma unroll
        for (int kk = 0; kk < 16; kk++) {
            float4 a = *(float4*)&As[kk][r0];
            float4 b = *(float4*)&Bs[kk][c0];
            float av[4] = {a.x,a.y,a.z,a.w};
            float bv[4] = {b.x,b.y,b.z,b.w};
            #pragma unroll
            for (int i = 0; i < 4; i++)
                #pragma unroll
                for (int j = 0; j < 4; j++)
                    acc[i][j] += av[i] * bv[j];
        }
        __syncthreads();
    }

    float4 bias = *(const float4*)(bo + n0 + c0);
    float bv[4] = {bias.x, bias.y, bias.z, bias.w};
    #pragma unroll
    for (int i = 0; i < 4; i++) {
        int m = m0 + r0 + i;
        float4 val = make_float4(acc[i][0]+bv[0], acc[i][1]+bv[1],
                                 acc[i][2]+bv[2], acc[i][3]+bv[3]);
        *(float4*)(out + (size_t)m * EE + n0 + c0) = val;
    }
}

// ---------------- launch ------------------------------------------------------
extern "C" void kernel_launch(void* const* d_in, const int* in_sizes, int n_in,
                              void* d_out, int out_size)
{
    const float* x  = (const float*)d_in[0];
    const float* Wq = (const float*)d_in[1];
    const float* Wk = (const float*)d_in[2];
    const float* Wv = (const float*)d_in[3];
    const float* Wo = (const float*)d_in[4];
    const float* bo = (const float*)d_in[5];
    float* out = (float*)d_out;

    float *q, *k, *v, *att;
    cudaGetSymbolAddress((void**)&q,   g_q);
    cudaGetSymbolAddress((void**)&k,   g_k);
    cudaGetSymbolAddress((void**)&v,   g_v);
    cudaGetSymbolAddress((void**)&att, g_att);

    const int smem_attn = 4 * 64 * 65 * (int)sizeof(float);   // 66,560 B
    cudaFuncSetAttribute(attn_kernel, cudaFuncAttributeMaxDynamicSharedMemorySize,
                         smem_attn);

    dim3 gproj(MM / 64, HH);
    proj_kernel<<<gproj, 256>>>(x, Wq, q);
    proj_kernel<<<gproj, 256>>>(x, Wk, k);
    proj_kernel<<<gproj, 256>>>(x, Wv, v);

    dim3 gattn(TT / 64, BB * HH);
    attn_kernel<<<gattn, 256, smem_attn>>>(q, k, v, att);

    dim3 goproj(MM / 64, EE / 64);
    oproj_kernel<<<goproj, 256>>>(att, Wo, bo, out);
}

// round 3
// speedup vs baseline: 1.5984x; 1.5984x over previous
#include <cuda_runtime.h>
#include <cuda_bf16.h>
#include <cstdint>
#include <math.h>

#define BB 4
#define TT 2048
#define EE 1024
#define HH 16
#define HDD 64
#define MM (BB*TT)          // 8192

// ---------------------------------------------------------------- scratch ----
__device__ float g_q[BB*HH*TT*HDD];
__device__ float g_k[BB*HH*TT*HDD];
__device__ float g_v[BB*HH*TT*HDD];
__device__ __nv_bfloat16 g_xhi[MM*EE],  g_xlo[MM*EE];
__device__ __nv_bfloat16 g_ahi[MM*EE],  g_alo[MM*EE];     // attention out (concat heads)
__device__ __nv_bfloat16 g_wqhi[EE*EE], g_wqlo[EE*EE];    // transposed: [h*64+d][e]
__device__ __nv_bfloat16 g_wkhi[EE*EE], g_wklo[EE*EE];
__device__ __nv_bfloat16 g_wvhi[EE*EE], g_wvlo[EE*EE];
__device__ __nv_bfloat16 g_wohi[EE*EE], g_wolo[EE*EE];    // natural: [n][k]

// ---------------------------------------------------------------- helpers ----
__device__ __forceinline__ uint32_t smem_u32(const void* p) {
    uint32_t a;
    asm("{ .reg .u64 t; cvta.to.shared.u64 t, %1; cvt.u32.u64 %0, t; }" : "=r"(a) : "l"(p));
    return a;
}
__device__ __forceinline__ void cp16(uint32_t saddr, const void* g) {
    asm volatile("cp.async.cg.shared.global [%0], [%1], 16;" :: "r"(saddr), "l"(g));
}
#define CP_COMMIT() asm volatile("cp.async.commit_group;" ::: "memory")
#define CP_WAIT(n)  asm volatile("cp.async.wait_group %0;" :: "n"(n) : "memory")

__device__ __forceinline__ void ldm_x4(uint32_t* r, uint32_t addr) {
    asm volatile("ldmatrix.sync.aligned.m8n8.x4.shared.b16 {%0,%1,%2,%3}, [%4];"
                 : "=r"(r[0]), "=r"(r[1]), "=r"(r[2]), "=r"(r[3]) : "r"(addr));
}
__device__ __forceinline__ void ldm_x2(uint32_t* r, uint32_t addr) {
    asm volatile("ldmatrix.sync.aligned.m8n8.x2.shared.b16 {%0,%1}, [%2];"
                 : "=r"(r[0]), "=r"(r[1]) : "r"(addr));
}
__device__ __forceinline__ void mma16816(float* c, const uint32_t* a, const uint32_t* b) {
    asm volatile("mma.sync.aligned.m16n8k16.row.col.f32.bf16.bf16.f32 "
                 "{%0,%1,%2,%3}, {%4,%5,%6,%7}, {%8,%9}, {%0,%1,%2,%3};"
                 : "+f"(c[0]), "+f"(c[1]), "+f"(c[2]), "+f"(c[3])
                 : "r"(a[0]), "r"(a[1]), "r"(a[2]), "r"(a[3]), "r"(b[0]), "r"(b[1]));
}

// ---------------------------------------------------------------- converts --
__device__ __forceinline__ void split1(float v, ushort& h, ushort& l) {
    __nv_bfloat16 hb = __float2bfloat16(v);
    float rem = v - __bfloat162float(hb);
    __nv_bfloat16 lb = __float2bfloat16(rem);
    h = __bfloat16_as_ushort(hb); l = __bfloat16_as_ushort(lb);
}

__global__ __launch_bounds__(256) void conv_x_kernel(const float* __restrict__ x,
        __nv_bfloat16* __restrict__ hi, __nv_bfloat16* __restrict__ lo) {
    size_t i = ((size_t)blockIdx.x * 256 + threadIdx.x) * 8;
    float4 a = *(const float4*)(x + i);
    float4 b = *(const float4*)(x + i + 4);
    float v[8] = {a.x,a.y,a.z,a.w,b.x,b.y,b.z,b.w};
    ushort hs[8], ls[8];
    #pragma unroll
    for (int j = 0; j < 8; j++) split1(v[j], hs[j], ls[j]);
    uint4 ph = make_uint4(hs[0]|(hs[1]<<16), hs[2]|(hs[3]<<16), hs[4]|(hs[5]<<16), hs[6]|(hs[7]<<16));
    uint4 pl = make_uint4(ls[0]|(ls[1]<<16), ls[2]|(ls[3]<<16), ls[4]|(ls[5]<<16), ls[6]|(ls[7]<<16));
    *(uint4*)(hi + i) = ph;
    *(uint4*)(lo + i) = pl;
}

// W[h][e][d] -> WT[h*64+d][e]
__global__ __launch_bounds__(256) void conv_wT_kernel(const float* __restrict__ W,
        __nv_bfloat16* __restrict__ hi, __nv_bfloat16* __restrict__ lo) {
    int idx = blockIdx.x * 256 + threadIdx.x;
    int row = idx >> 10, e = idx & 1023;
    int h = row >> 6, d = row & 63;
    float v = W[((size_t)h * EE + e) * HDD + d];
    ushort hs, ls; split1(v, hs, ls);
    hi[idx] = __ushort_as_bfloat16(hs);
    lo[idx] = __ushort_as_bfloat16(ls);
}

__global__ __launch_bounds__(256) void conv_wo_kernel(const float* __restrict__ W,
        __nv_bfloat16* __restrict__ hi, __nv_bfloat16* __restrict__ lo) {
    int idx = blockIdx.x * 256 + threadIdx.x;
    float v = W[idx];
    ushort hs, ls; split1(v, hs, ls);
    hi[idx] = __ushort_as_bfloat16(hs);
    lo[idx] = __ushort_as_bfloat16(ls);
}

// ------------------------------------------------ HMMA split-bf16 GEMM -------
// C[8192,1024] = A[8192,1024] @ B[1024,1024]^T (B stored [n][k]), fp32 accum.
// CTA 128x128, BK=32, 256 threads (8 warps, 2x4), warp tile 64x32.
#define ROWB   80                     // 64B data + 16B pad per 32-bf16 row
#define MATB   (128*ROWB)             // 10240 B per matrix tile
#define OFF_AH 0
#define OFF_AL (1*MATB)
#define OFF_BH (2*MATB)
#define OFF_BL (3*MATB)
#define STAGE  (4*MATB)               // 40960 B

__device__ __forceinline__ void stage_load(uint32_t base,
    const __nv_bfloat16* __restrict__ Ahi, const __nv_bfloat16* __restrict__ Alo,
    const __nv_bfloat16* __restrict__ Bhi, const __nv_bfloat16* __restrict__ Blo,
    int m0, int n0, int k0, int tid)
{
    #pragma unroll
    for (int p = 0; p < 2; p++) {
        int chunk = p * 256 + tid;          // 0..511
        int row = chunk >> 2, ch = chunk & 3;
        uint32_t so = row * ROWB + ch * 16;
        size_t ga = (size_t)(m0 + row) * EE + k0 + ch * 8;
        size_t gb = (size_t)(n0 + row) * EE + k0 + ch * 8;
        cp16(base + OFF_AH + so, Ahi + ga);
        cp16(base + OFF_AL + so, Alo + ga);
        cp16(base + OFF_BH + so, Bhi + gb);
        cp16(base + OFF_BL + so, Blo + gb);
    }
}

template <int MODE>   // 0: write (b,h,t,d) fp32; 1: write [m][n] fp32 + bias
__global__ __launch_bounds__(256)
void gemm_kernel(const __nv_bfloat16* __restrict__ Ahi, const __nv_bfloat16* __restrict__ Alo,
                 const __nv_bfloat16* __restrict__ Bhi, const __nv_bfloat16* __restrict__ Blo,
                 const float* __restrict__ bias, float* __restrict__ C)
{
    extern __shared__ char smem[];
    const int tid = threadIdx.x;
    const int lane = tid & 31, wid = tid >> 5;
    const int wm = wid >> 2, wn = wid & 3;          // warp grid 2x4
    const int m0 = blockIdx.x * 128;
    const int n0 = blockIdx.y * 128;
    const uint32_t sb = smem_u32(smem);

    float acc[4][4][4];
    #pragma unroll
    for (int i = 0; i < 4; i++)
        #pragma unroll
        for (int j = 0; j < 4; j++)
            #pragma unroll
            for (int r = 0; r < 4; r++) acc[i][j][r] = 0.f;

    // ldmatrix source addresses (within a stage)
    const uint32_t a_row = lane & 15, a_half = lane >> 4;      // A: x4
    const uint32_t b_row = lane & 7,  b_half = (lane >> 3) & 1; // B: x2

    stage_load(sb, Ahi, Alo, Bhi, Blo, m0, n0, 0, tid);
    CP_COMMIT();

    for (int kt = 0; kt < EE / 32; kt++) {
        if (kt + 1 < EE / 32) {
            stage_load(sb + ((kt + 1) & 1) * STAGE, Ahi, Alo, Bhi, Blo,
                       m0, n0, (kt + 1) * 32, tid);
            CP_COMMIT();
            CP_WAIT(1);
        } else {
            CP_WAIT(0);
        }
        __syncthreads();

        const uint32_t st = sb + (kt & 1) * STAGE;
        #pragma unroll
        for (int ks = 0; ks < 2; ks++) {
            uint32_t ah[4][4], al[4][4], bh[4][2], bl[4][2];
            const uint32_t kb = (ks * 16 + a_half * 8) * 2;    // A k-offset bytes
            const uint32_t kbB = (ks * 16 + b_half * 8) * 2;   // B k-offset bytes
            #pragma unroll
            for (int mi = 0; mi < 4; mi++) {
                uint32_t ro = (wm * 64 + mi * 16 + a_row) * ROWB + kb;
                ldm_x4(ah[mi], st + OFF_AH + ro);
            }
            #pragma unroll
            for (int ni = 0; ni < 4; ni++) {
                uint32_t ro = (wn * 32 + ni * 8 + b_row) * ROWB + kbB;
                ldm_x2(bh[ni], st + OFF_BH + ro);
            }
            #pragma unroll
            for (int mi = 0; mi < 4; mi++)
                #pragma unroll
                for (int ni = 0; ni < 4; ni++)
                    mma16816(acc[mi][ni], ah[mi], bh[ni]);
            #pragma unroll
            for (int ni = 0; ni < 4; ni++) {
                uint32_t ro = (wn * 32 + ni * 8 + b_row) * ROWB + kbB;
                ldm_x2(bl[ni], st + OFF_BL + ro);
            }
            #pragma unroll
            for (int mi = 0; mi < 4; mi++)
                #pragma unroll
                for (int ni = 0; ni < 4; ni++)
                    mma16816(acc[mi][ni], ah[mi], bl[ni]);
            #pragma unroll
            for (int mi = 0; mi < 4; mi++) {
                uint32_t ro = (wm * 64 + mi * 16 + a_row) * ROWB + kb;
                ldm_x4(al[mi], st + OFF_AL + ro);
            }
            #pragma unroll
            for (int mi = 0; mi < 4; mi++)
                #pragma unroll
                for (int ni = 0; ni < 4; ni++)
                    mma16816(acc[mi][ni], al[mi], bh[ni]);
        }
        __syncthreads();
    }

    // epilogue
    const int rbase = lane >> 2;             // 0..7
    const int cbase = (lane & 3) * 2;
    #pragma unroll
    for (int mi = 0; mi < 4; mi++) {
        #pragma unroll
        for (int ni = 0; ni < 4; ni++) {
            int mrow = m0 + wm * 64 + mi * 16 + rbase;
            int ncol = n0 + wn * 32 + ni * 8 + cbase;
            if (MODE == 0) {
                int head = ncol >> 6, d = ncol & 63;
                int b = mrow >> 11, t = mrow & 2047;
                float* dst = C + ((size_t)(b * HH + head) * TT + t) * HDD + d;
                *(float2*)dst = make_float2(acc[mi][ni][0], acc[mi][ni][1]);
                *(float2*)(dst + 8 * HDD) = make_float2(acc[mi][ni][2], acc[mi][ni][3]);
            } else {
                float2 bv = *(const float2*)(bias + ncol);
                float* dst = C + (size_t)mrow * EE + ncol;
                *(float2*)dst = make_float2(acc[mi][ni][0] + bv.x, acc[mi][ni][1] + bv.y);
                *(float2*)(dst + 8 * EE) = make_float2(acc[mi][ni][2] + bv.x,
                                                       acc[mi][ni][3] + bv.y);
            }
        }
    }
}

// ---------------- fp32 flash attention (causal), epilogue -> split bf16 ------
__global__ __launch_bounds__(256)
void attn_kernel(const float* __restrict__ q, const float* __restrict__ k,
                 const float* __restrict__ v,
                 __nv_bfloat16* __restrict__ ahi, __nv_bfloat16* __restrict__ alo)
{
    extern __shared__ float sm[];
    float (*Qs)[65] = (float(*)[65])(sm);
    float (*Ks)[65] = (float(*)[65])(sm + 64*65);
    float (*Vs)[65] = (float(*)[65])(sm + 2*64*65);
    float (*Ps)[65] = (float(*)[65])(sm + 3*64*65);

    const int qi = blockIdx.x;
    const int bh = blockIdx.y;
    const size_t base = (size_t)bh * TT * HDD;

    const int tid = threadIdx.x;
    const int ty = tid >> 4, tx = tid & 15;
    const int r0 = ty * 4, c0 = tx * 4;
    const int rr = tid >> 4;
    const int d4 = (tid & 15) * 4;

    #pragma unroll
    for (int p = 0; p < 4; p++) {
        int row = p * 16 + rr;
        float4 qv = *(const float4*)(q + base + (size_t)(qi*64 + row) * HDD + d4);
        Qs[row][d4+0] = qv.x; Qs[row][d4+1] = qv.y;
        Qs[row][d4+2] = qv.z; Qs[row][d4+3] = qv.w;
    }

    float mstat[4], lstat[4], o[4][4];
    #pragma unroll
    for (int i = 0; i < 4; i++) {
        mstat[i] = -1e30f; lstat[i] = 0.f;
        #pragma unroll
        for (int j = 0; j < 4; j++) o[i][j] = 0.f;
    }
    const float scale = 0.125f;

    for (int j = 0; j <= qi; j++) {
        __syncthreads();
        #pragma unroll
        for (int p = 0; p < 4; p++) {
            int row = p * 16 + rr;
            float4 kv = *(const float4*)(k + base + (size_t)(j*64 + row) * HDD + d4);
            Ks[row][d4+0] = kv.x; Ks[row][d4+1] = kv.y;
            Ks[row][d4+2] = kv.z; Ks[row][d4+3] = kv.w;
            float4 vv = *(const float4*)(v + base + (size_t)(j*64 + row) * HDD + d4);
            Vs[row][d4+0] = vv.x; Vs[row][d4+1] = vv.y;
            Vs[row][d4+2] = vv.z; Vs[row][d4+3] = vv.w;
        }
        __syncthreads();

        float s[4][4] = {};
        #pragma unroll 8
        for (int kd = 0; kd < 64; kd++) {
            float qreg[4], kreg[4];
            #pragma unroll
            for (int i = 0; i < 4; i++) qreg[i] = Qs[r0+i][kd];
            #pragma unroll
            for (int i = 0; i < 4; i++) kreg[i] = Ks[c0+i][kd];
            #pragma unroll
            for (int i = 0; i < 4; i++)
                #pragma unroll
                for (int jj = 0; jj < 4; jj++)
                    s[i][jj] += qreg[i] * kreg[jj];
        }

        #pragma unroll
        for (int i = 0; i < 4; i++)
            #pragma unroll
            for (int jj = 0; jj < 4; jj++) {
                float sv = s[i][jj] * scale;
                if (j == qi && (c0 + jj) > (r0 + i)) sv = -1e30f;
                s[i][jj] = sv;
            }

        #pragma unroll
        for (int i = 0; i < 4; i++) {
            float rm = fmaxf(fmaxf(s[i][0], s[i][1]), fmaxf(s[i][2], s[i][3]));
            #pragma unroll
            for (int off = 8; off > 0; off >>= 1)
                rm = fmaxf(rm, __shfl_xor_sync(0xffffffffu, rm, off, 16));
            float newm = fmaxf(mstat[i], rm);
            float corr = __expf(mstat[i] - newm);
            float rs = 0.f;
            #pragma unroll
            for (int jj = 0; jj < 4; jj++) {
                float p = __expf(s[i][jj] - newm);
                s[i][jj] = p;
                rs += p;
            }
            #pragma unroll
            for (int off = 8; off > 0; off >>= 1)
                rs += __shfl_xor_sync(0xffffffffu, rs, off, 16);
            lstat[i] = lstat[i] * corr + rs;
            mstat[i] = newm;
            #pragma unroll
            for (int jj = 0; jj < 4; jj++) o[i][jj] *= corr;
        }

        #pragma unroll
        for (int i = 0; i < 4; i++)
            #pragma unroll
            for (int jj = 0; jj < 4; jj++)
                Ps[r0+i][c0+jj] = s[i][jj];
        __syncthreads();

        #pragma unroll 8
        for (int ss = 0; ss < 64; ss++) {
            float pr[4], vv[4];
            #pragma unroll
            for (int i = 0; i < 4; i++) pr[i] = Ps[r0+i][ss];
            #pragma unroll
            for (int jj = 0; jj < 4; jj++) vv[jj] = Vs[ss][c0+jj];
            #pragma unroll
            for (int i = 0; i < 4; i++)
                #pragma unroll
                for (int jj = 0; jj < 4; jj++)
                    o[i][jj] += pr[i] * vv[jj];
        }
    }

    const int b = bh / HH, h = bh % HH;
    #pragma unroll
    for (int i = 0; i < 4; i++) {
        float inv = 1.f / lstat[i];
        int t = qi * 64 + r0 + i;
        size_t off = ((size_t)(b * TT + t)) * EE + h * HDD + c0;
        ushort hs[4], ls[4];
        #pragma unroll
        for (int jj = 0; jj < 4; jj++) split1(o[i][jj] * inv, hs[jj], ls[jj]);
        uint2 ph = make_uint2(hs[0] | (hs[1] << 16), hs[2] | (hs[3] << 16));
        uint2 pl = make_uint2(ls[0] | (ls[1] << 16), ls[2] | (ls[3] << 16));
        *(uint2*)(ahi + off) = ph;
        *(uint2*)(alo + off) = pl;
    }
}

// ---------------------------------------------------------------- launch ----
extern "C" void kernel_launch(void* const* d_in, const int* in_sizes, int n_in,
                              void* d_out, int out_size)
{
    const float* x  = (const float*)d_in[0];
    const float* Wq = (const float*)d_in[1];
    const float* Wk = (const float*)d_in[2];
    const float* Wv = (const float*)d_in[3];
    const float* Wo = (const float*)d_in[4];
    const float* bo = (const float*)d_in[5];
    float* out = (float*)d_out;

    float *q, *k, *v;
    __nv_bfloat16 *xhi, *xlo, *ahi, *alo;
    __nv_bfloat16 *wqh, *wql, *wkh, *wkl, *wvh, *wvl, *woh, *wol;
    cudaGetSymbolAddress((void**)&q,   g_q);
    cudaGetSymbolAddress((void**)&k,   g_k);
    cudaGetSymbolAddress((void**)&v,   g_v);
    cudaGetSymbolAddress((void**)&xhi, g_xhi);
    cudaGetSymbolAddress((void**)&xlo, g_xlo);
    cudaGetSymbolAddress((void**)&ahi, g_ahi);
    cudaGetSymbolAddress((void**)&alo, g_alo);
    cudaGetSymbolAddress((void**)&wqh, g_wqhi);
    cudaGetSymbolAddress((void**)&wql, g_wqlo);
    cudaGetSymbolAddress((void**)&wkh, g_wkhi);
    cudaGetSymbolAddress((void**)&wkl, g_wklo);
    cudaGetSymbolAddress((void**)&wvh, g_wvhi);
    cudaGetSymbolAddress((void**)&wvl, g_wvlo);
    cudaGetSymbolAddress((void**)&woh, g_wohi);
    cudaGetSymbolAddress((void**)&wol, g_wolo);

    const int smem_gemm = 2 * STAGE;   // 81920 B
    cudaFuncSetAttribute(gemm_kernel<0>, cudaFuncAttributeMaxDynamicSharedMemorySize, smem_gemm);
    cudaFuncSetAttribute(gemm_kernel<1>, cudaFuncAttributeMaxDynamicSharedMemorySize, smem_gemm);
    const int smem_attn = 4 * 64 * 65 * (int)sizeof(float);
    cudaFuncSetAttribute(attn_kernel, cudaFuncAttributeMaxDynamicSharedMemorySize, smem_attn);

    conv_x_kernel<<<MM * EE / (256 * 8), 256>>>(x, xhi, xlo);
    conv_wT_kernel<<<EE * EE / 256, 256>>>(Wq, wqh, wql);
    conv_wT_kernel<<<EE * EE / 256, 256>>>(Wk, wkh, wkl);
    conv_wT_kernel<<<EE * EE / 256, 256>>>(Wv, wvh, wvl);
    conv_wo_kernel<<<EE * EE / 256, 256>>>(Wo, woh, wol);

    dim3 gg(MM / 128, EE / 128);
    gemm_kernel<0><<<gg, 256, smem_gemm>>>(xhi, xlo, wqh, wql, nullptr, q);
    gemm_kernel<0><<<gg, 256, smem_gemm>>>(xhi, xlo, wkh, wkl, nullptr, k);
    gemm_kernel<0><<<gg, 256, smem_gemm>>>(xhi, xlo, wvh, wvl, nullptr, v);

    dim3 ga(TT / 64, BB * HH);
    attn_kernel<<<ga, 256, smem_attn>>>(q, k, v, ahi, alo);

    gemm_kernel<1><<<gg, 256, smem_gemm>>>(ahi, alo, woh, wol, bo, out);
}

// round 4
// speedup vs baseline: 2.6688x; 1.6697x over previous
#include <cuda_runtime.h>
#include <cuda_bf16.h>
#include <cstdint>
#include <math.h>

#define BB 4
#define TT 2048
#define EE 1024
#define HH 16
#define HDD 64
#define MM (BB*TT)          // 8192

// ---------------------------------------------------------------- scratch ----
__device__ __nv_bfloat16 g_qhi[MM*EE], g_qlo[MM*EE];      // (b,h,t,d), pre-scaled
__device__ __nv_bfloat16 g_khi[MM*EE], g_klo[MM*EE];
__device__ __nv_bfloat16 g_vhi[MM*EE], g_vlo[MM*EE];
__device__ __nv_bfloat16 g_xhi[MM*EE], g_xlo[MM*EE];
__device__ __nv_bfloat16 g_ahi[MM*EE], g_alo[MM*EE];      // attention out (concat heads)
__device__ __nv_bfloat16 g_wqhi[EE*EE], g_wqlo[EE*EE];    // transposed: [h*64+d][e]
__device__ __nv_bfloat16 g_wkhi[EE*EE], g_wklo[EE*EE];
__device__ __nv_bfloat16 g_wvhi[EE*EE], g_wvlo[EE*EE];
__device__ __nv_bfloat16 g_wohi[EE*EE], g_wolo[EE*EE];    // natural: [n][k]

// ---------------------------------------------------------------- helpers ----
__device__ __forceinline__ uint32_t smem_u32(const void* p) {
    uint32_t a;
    asm("{ .reg .u64 t; cvta.to.shared.u64 t, %1; cvt.u32.u64 %0, t; }" : "=r"(a) : "l"(p));
    return a;
}
__device__ __forceinline__ void cp16(uint32_t saddr, const void* g) {
    asm volatile("cp.async.cg.shared.global [%0], [%1], 16;" :: "r"(saddr), "l"(g));
}
#define CP_COMMIT() asm volatile("cp.async.commit_group;" ::: "memory")
#define CP_WAIT(n)  asm volatile("cp.async.wait_group %0;" :: "n"(n) : "memory")

__device__ __forceinline__ void ldm_x4(uint32_t* r, uint32_t addr) {
    asm volatile("ldmatrix.sync.aligned.m8n8.x4.shared.b16 {%0,%1,%2,%3}, [%4];"
                 : "=r"(r[0]), "=r"(r[1]), "=r"(r[2]), "=r"(r[3]) : "r"(addr));
}
__device__ __forceinline__ void ldm_x2(uint32_t* r, uint32_t addr) {
    asm volatile("ldmatrix.sync.aligned.m8n8.x2.shared.b16 {%0,%1}, [%2];"
                 : "=r"(r[0]), "=r"(r[1]) : "r"(addr));
}
__device__ __forceinline__ void ldm_x2t(uint32_t* r, uint32_t addr) {
    asm volatile("ldmatrix.sync.aligned.m8n8.x2.trans.shared.b16 {%0,%1}, [%2];"
                 : "=r"(r[0]), "=r"(r[1]) : "r"(addr));
}
__device__ __forceinline__ void mma16816(float* c, const uint32_t* a, const uint32_t* b) {
    asm volatile("mma.sync.aligned.m16n8k16.row.col.f32.bf16.bf16.f32 "
                 "{%0,%1,%2,%3}, {%4,%5,%6,%7}, {%8,%9}, {%0,%1,%2,%3};"
                 : "+f"(c[0]), "+f"(c[1]), "+f"(c[2]), "+f"(c[3])
                 : "r"(a[0]), "r"(a[1]), "r"(a[2]), "r"(a[3]), "r"(b[0]), "r"(b[1]));
}

__device__ __forceinline__ void split1(float v, ushort& h, ushort& l) {
    __nv_bfloat16 hb = __float2bfloat16(v);
    float rem = v - __bfloat162float(hb);
    __nv_bfloat16 lb = __float2bfloat16(rem);
    h = __bfloat16_as_ushort(hb); l = __bfloat16_as_ushort(lb);
}
__device__ __forceinline__ void split2(float a, float b, uint32_t& hi, uint32_t& lo) {
    ushort h0, l0, h1, l1;
    split1(a, h0, l0); split1(b, h1, l1);
    hi = (uint32_t)h0 | ((uint32_t)h1 << 16);
    lo = (uint32_t)l0 | ((uint32_t)l1 << 16);
}

// ---------------------------------------------------------------- converts --
__global__ __launch_bounds__(256) void conv_x_kernel(const float* __restrict__ x,
        __nv_bfloat16* __restrict__ hi, __nv_bfloat16* __restrict__ lo) {
    size_t i = ((size_t)blockIdx.x * 256 + threadIdx.x) * 8;
    float4 a = *(const float4*)(x + i);
    float4 b = *(const float4*)(x + i + 4);
    float v[8] = {a.x,a.y,a.z,a.w,b.x,b.y,b.z,b.w};
    ushort hs[8], ls[8];
    #pragma unroll
    for (int j = 0; j < 8; j++) split1(v[j], hs[j], ls[j]);
    uint4 ph = make_uint4(hs[0]|(hs[1]<<16), hs[2]|(hs[3]<<16), hs[4]|(hs[5]<<16), hs[6]|(hs[7]<<16));
    uint4 pl = make_uint4(ls[0]|(ls[1]<<16), ls[2]|(ls[3]<<16), ls[4]|(ls[5]<<16), ls[6]|(ls[7]<<16));
    *(uint4*)(hi + i) = ph;
    *(uint4*)(lo + i) = pl;
}

// W[h][e][d] -> WT[h*64+d][e]
__global__ __launch_bounds__(256) void conv_wT_kernel(const float* __restrict__ W,
        __nv_bfloat16* __restrict__ hi, __nv_bfloat16* __restrict__ lo) {
    int idx = blockIdx.x * 256 + threadIdx.x;
    int row = idx >> 10, e = idx & 1023;
    int h = row >> 6, d = row & 63;
    float v = W[((size_t)h * EE + e) * HDD + d];
    ushort hs, ls; split1(v, hs, ls);
    hi[idx] = __ushort_as_bfloat16(hs);
    lo[idx] = __ushort_as_bfloat16(ls);
}

__global__ __launch_bounds__(256) void conv_wo_kernel(const float* __restrict__ W,
        __nv_bfloat16* __restrict__ hi, __nv_bfloat16* __restrict__ lo) {
    int idx = blockIdx.x * 256 + threadIdx.x;
    float v = W[idx];
    ushort hs, ls; split1(v, hs, ls);
    hi[idx] = __ushort_as_bfloat16(hs);
    lo[idx] = __ushort_as_bfloat16(ls);
}

// ------------------------------------------------ HMMA split-bf16 GEMM -------
// CTA 128x128, BK=32, 256 threads (8 warps, 2x4), warp tile 64x32.
#define ROWB   80
#define MATB   (128*ROWB)
#define OFF_AH 0
#define OFF_AL (1*MATB)
#define OFF_BH (2*MATB)
#define OFF_BL (3*MATB)
#define STAGE  (4*MATB)               // 40960 B

__device__ __forceinline__ void stage_load(uint32_t base,
    const __nv_bfloat16* __restrict__ Ahi, const __nv_bfloat16* __restrict__ Alo,
    const __nv_bfloat16* __restrict__ Bhi, const __nv_bfloat16* __restrict__ Blo,
    int m0, int n0, int k0, int tid)
{
    #pragma unroll
    for (int p = 0; p < 2; p++) {
        int chunk = p * 256 + tid;
        int row = chunk >> 2, ch = chunk & 3;
        uint32_t so = row * ROWB + ch * 16;
        size_t ga = (size_t)(m0 + row) * EE + k0 + ch * 8;
        size_t gb = (size_t)(n0 + row) * EE + k0 + ch * 8;
        cp16(base + OFF_AH + so, Ahi + ga);
        cp16(base + OFF_AL + so, Alo + ga);
        cp16(base + OFF_BH + so, Bhi + gb);
        cp16(base + OFF_BL + so, Blo + gb);
    }
}

// MODE 0: split-bf16 output (b,h,t,d) with scale. MODE 1: fp32 [m][n] + bias.
template <int MODE>
__global__ __launch_bounds__(256)
void gemm_kernel(const __nv_bfloat16* __restrict__ Ahi, const __nv_bfloat16* __restrict__ Alo,
                 const __nv_bfloat16* __restrict__ Bhi, const __nv_bfloat16* __restrict__ Blo,
                 const float* __restrict__ bias, float* __restrict__ C,
                 __nv_bfloat16* __restrict__ Chi, __nv_bfloat16* __restrict__ Clo,
                 float scale)
{
    extern __shared__ char smem[];
    const int tid = threadIdx.x;
    const int lane = tid & 31, wid = tid >> 5;
    const int wm = wid >> 2, wn = wid & 3;
    const int m0 = blockIdx.x * 128;
    const int n0 = blockIdx.y * 128;
    const uint32_t sb = smem_u32(smem);

    float acc[4][4][4];
    #pragma unroll
    for (int i = 0; i < 4; i++)
        #pragma unroll
        for (int j = 0; j < 4; j++)
            #pragma unroll
            for (int r = 0; r < 4; r++) acc[i][j][r] = 0.f;

    const uint32_t a_row = lane & 15, a_half = lane >> 4;
    const uint32_t b_row = lane & 7,  b_half = (lane >> 3) & 1;

    stage_load(sb, Ahi, Alo, Bhi, Blo, m0, n0, 0, tid);
    CP_COMMIT();

    for (int kt = 0; kt < EE / 32; kt++) {
        if (kt + 1 < EE / 32) {
            stage_load(sb + ((kt + 1) & 1) * STAGE, Ahi, Alo, Bhi, Blo,
                       m0, n0, (kt + 1) * 32, tid);
            CP_COMMIT();
            CP_WAIT(1);
        } else {
            CP_WAIT(0);
        }
        __syncthreads();

        const uint32_t st = sb + (kt & 1) * STAGE;
        #pragma unroll
        for (int ks = 0; ks < 2; ks++) {
            uint32_t ah[4][4], al[4][4], bh[4][2], bl[4][2];
            const uint32_t kb  = (ks * 16 + a_half * 8) * 2;
            const uint32_t kbB = (ks * 16 + b_half * 8) * 2;
            #pragma unroll
            for (int mi = 0; mi < 4; mi++)
                ldm_x4(ah[mi], st + OFF_AH + (wm * 64 + mi * 16 + a_row) * ROWB + kb);
            #pragma unroll
            for (int ni = 0; ni < 4; ni++)
                ldm_x2(bh[ni], st + OFF_BH + (wn * 32 + ni * 8 + b_row) * ROWB + kbB);
            #pragma unroll
            for (int mi = 0; mi < 4; mi++)
                #pragma unroll
                for (int ni = 0; ni < 4; ni++)
                    mma16816(acc[mi][ni], ah[mi], bh[ni]);
            #pragma unroll
            for (int ni = 0; ni < 4; ni++)
                ldm_x2(bl[ni], st + OFF_BL + (wn * 32 + ni * 8 + b_row) * ROWB + kbB);
            #pragma unroll
            for (int mi = 0; mi < 4; mi++)
                #pragma unroll
                for (int ni = 0; ni < 4; ni++)
                    mma16816(acc[mi][ni], ah[mi], bl[ni]);
            #pragma unroll
            for (int mi = 0; mi < 4; mi++)
                ldm_x4(al[mi], st + OFF_AL + (wm * 64 + mi * 16 + a_row) * ROWB + kb);
            #pragma unroll
            for (int mi = 0; mi < 4; mi++)
                #pragma unroll
                for (int ni = 0; ni < 4; ni++)
                    mma16816(acc[mi][ni], al[mi], bh[ni]);
        }
        __syncthreads();
    }

    const int rbase = lane >> 2;
    const int cbase = (lane & 3) * 2;
    #pragma unroll
    for (int mi = 0; mi < 4; mi++) {
        #pragma unroll
        for (int ni = 0; ni < 4; ni++) {
            int mrow = m0 + wm * 64 + mi * 16 + rbase;
            int ncol = n0 + wn * 32 + ni * 8 + cbase;
            if (MODE == 0) {
                int head = ncol >> 6, d = ncol & 63;
                int b = mrow >> 11, t = mrow & 2047;
                size_t o0 = ((size_t)(b * HH + head) * TT + t) * HDD + d;
                size_t o1 = o0 + 8 * HDD;   // row +8
                uint32_t h0, l0, h1, l1;
                split2(acc[mi][ni][0] * scale, acc[mi][ni][1] * scale, h0, l0);
                split2(acc[mi][ni][2] * scale, acc[mi][ni][3] * scale, h1, l1);
                *(uint32_t*)(Chi + o0) = h0; *(uint32_t*)(Clo + o0) = l0;
                *(uint32_t*)(Chi + o1) = h1; *(uint32_t*)(Clo + o1) = l1;
            } else {
                float2 bv = *(const float2*)(bias + ncol);
                float* dst = C + (size_t)mrow * EE + ncol;
                *(float2*)dst = make_float2(acc[mi][ni][0] + bv.x, acc[mi][ni][1] + bv.y);
                *(float2*)(dst + 8 * EE) = make_float2(acc[mi][ni][2] + bv.x,
                                                       acc[mi][ni][3] + bv.y);
            }
        }
    }
}

// ---------------- HMMA flash attention (causal), split-bf16 throughout -------
// CTA: 64 q-rows x one bh. 4 warps (16 rows each). kv tile 64.
#define AT_RW   144                       // 128B row + 16B pad
#define AT_MAT  (64*AT_RW)                // 9216 B
#define AT_Q    0                         // QH, QL
#define AT_ST   (2*AT_MAT)                // stages: [KH,KL,VH,VL] x2
#define AT_STAGE (4*AT_MAT)               // 36864
#define AT_SMEM (2*AT_MAT + 2*AT_STAGE)   // 92160

__device__ __forceinline__ void attn_load_kv(uint32_t dst,
    const __nv_bfloat16* kh, const __nv_bfloat16* kl,
    const __nv_bfloat16* vh, const __nv_bfloat16* vl,
    size_t base, int j, int tid)
{
    const __nv_bfloat16* mats[4] = {kh, kl, vh, vl};
    #pragma unroll
    for (int p = 0; p < 16; p++) {
        int idx = p * 128 + tid;          // 0..2047
        int mat = idx >> 9, rem = idx & 511;
        int row = rem >> 3, ch = rem & 7;
        cp16(dst + mat * AT_MAT + row * AT_RW + ch * 16,
             mats[mat] + base + (size_t)(j * 64 + row) * HDD + ch * 8);
    }
}

__global__ __launch_bounds__(128)
void attn_mma_kernel(const __nv_bfloat16* __restrict__ qh_g, const __nv_bfloat16* __restrict__ ql_g,
                     const __nv_bfloat16* __restrict__ kh_g, const __nv_bfloat16* __restrict__ kl_g,
                     const __nv_bfloat16* __restrict__ vh_g, const __nv_bfloat16* __restrict__ vl_g,
                     __nv_bfloat16* __restrict__ ahi, __nv_bfloat16* __restrict__ alo)
{
    extern __shared__ char smem[];
    const int tid = threadIdx.x, lane = tid & 31, w = tid >> 5;
    const int qi = (gridDim.x - 1) - blockIdx.x;      // longest CTAs first
    const int bh = blockIdx.y;
    const size_t base = (size_t)bh * TT * HDD;
    const uint32_t sb = smem_u32(smem);
    const uint32_t QH = sb + AT_Q, QL = QH + AT_MAT;
    const uint32_t ST = sb + AT_ST;

    // group 0: Q tile + kv stage 0
    {
        const __nv_bfloat16* qm[2] = {qh_g, ql_g};
        #pragma unroll
        for (int p = 0; p < 8; p++) {
            int idx = p * 128 + tid;      // 0..1023
            int mat = idx >> 9, rem = idx & 511;
            int row = rem >> 3, ch = rem & 7;
            cp16(QH + mat * AT_MAT + row * AT_RW + ch * 16,
                 qm[mat] + base + (size_t)(qi * 64 + row) * HDD + ch * 8);
        }
        attn_load_kv(ST, kh_g, kl_g, vh_g, vl_g, base, 0, tid);
        CP_COMMIT();
    }
    if (qi >= 1) {
        attn_load_kv(ST + AT_STAGE, kh_g, kl_g, vh_g, vl_g, base, 1, tid);
        CP_COMMIT();
        CP_WAIT(1);
    } else {
        CP_WAIT(0);
    }
    __syncthreads();

    // Q fragments (A operands), 4 k-steps
    uint32_t qh[4][4], ql[4][4];
    {
        const uint32_t a_row = lane & 15, a_half = lane >> 4;
        #pragma unroll
        for (int ks = 0; ks < 4; ks++) {
            uint32_t off = (w * 16 + a_row) * AT_RW + (ks * 16 + a_half * 8) * 2;
            ldm_x4(qh[ks], QH + off);
            ldm_x4(ql[ks], QL + off);
        }
    }

    float o[8][4];
    #pragma unroll
    for (int dt = 0; dt < 8; dt++)
        #pragma unroll
        for (int r = 0; r < 4; r++) o[dt][r] = 0.f;
    float m0 = -1e30f, m1 = -1e30f, l0 = 0.f, l1 = 0.f;

    const uint32_t b_row = lane & 7, b_half = (lane >> 3) & 1;
    const uint32_t t_row = lane & 15;
    const int rloc = (lane >> 2);                 // row in 0..7 within band
    const int cloc = (lane & 3) * 2;

    for (int j = 0; j <= qi; j++) {
        const uint32_t KHb = ST + (j & 1) * AT_STAGE;
        const uint32_t KLb = KHb + AT_MAT, VHb = KHb + 2*AT_MAT, VLb = KHb + 3*AT_MAT;

        // ---- S = Q K^T (3 split products) ----
        float s[8][4];
        #pragma unroll
        for (int nt = 0; nt < 8; nt++) {
            s[nt][0] = s[nt][1] = s[nt][2] = s[nt][3] = 0.f;
            #pragma unroll
            for (int ks = 0; ks < 4; ks++) {
                uint32_t off = (nt * 8 + b_row) * AT_RW + (ks * 16 + b_half * 8) * 2;
                uint32_t kh[2], kl[2];
                ldm_x2(kh, KHb + off);
                ldm_x2(kl, KLb + off);
                mma16816(s[nt], qh[ks], kh);
                mma16816(s[nt], qh[ks], kl);
                mma16816(s[nt], ql[ks], kh);
            }
        }

        // ---- causal mask (diagonal tile only) ----
        if (j == qi) {
            int r0g = w * 16 + rloc;
            #pragma unroll
            for (int nt = 0; nt < 8; nt++) {
                int col = nt * 8 + cloc;
                if (col     > r0g)     s[nt][0] = -1e30f;
                if (col + 1 > r0g)     s[nt][1] = -1e30f;
                if (col     > r0g + 8) s[nt][2] = -1e30f;
                if (col + 1 > r0g + 8) s[nt][3] = -1e30f;
            }
        }

        // ---- online softmax ----
        float mx0 = -1e30f, mx1 = -1e30f;
        #pragma unroll
        for (int nt = 0; nt < 8; nt++) {
            mx0 = fmaxf(mx0, fmaxf(s[nt][0], s[nt][1]));
            mx1 = fmaxf(mx1, fmaxf(s[nt][2], s[nt][3]));
        }
        mx0 = fmaxf(mx0, __shfl_xor_sync(0xffffffffu, mx0, 1));
        mx0 = fmaxf(mx0, __shfl_xor_sync(0xffffffffu, mx0, 2));
        mx1 = fmaxf(mx1, __shfl_xor_sync(0xffffffffu, mx1, 1));
        mx1 = fmaxf(mx1, __shfl_xor_sync(0xffffffffu, mx1, 2));
        float mn0 = fmaxf(m0, mx0), mn1 = fmaxf(m1, mx1);
        float cr0 = __expf(m0 - mn0), cr1 = __expf(m1 - mn1);
        float ls0 = 0.f, ls1 = 0.f;
        #pragma unroll
        for (int nt = 0; nt < 8; nt++) {
            s[nt][0] = __expf(s[nt][0] - mn0); ls0 += s[nt][0];
            s[nt][1] = __expf(s[nt][1] - mn0); ls0 += s[nt][1];
            s[nt][2] = __expf(s[nt][2] - mn1); ls1 += s[nt][2];
            s[nt][3] = __expf(s[nt][3] - mn1); ls1 += s[nt][3];
        }
        ls0 += __shfl_xor_sync(0xffffffffu, ls0, 1);
        ls0 += __shfl_xor_sync(0xffffffffu, ls0, 2);
        ls1 += __shfl_xor_sync(0xffffffffu, ls1, 1);
        ls1 += __shfl_xor_sync(0xffffffffu, ls1, 2);
        l0 = l0 * cr0 + ls0;  m0 = mn0;
        l1 = l1 * cr1 + ls1;  m1 = mn1;
        #pragma unroll
        for (int dt = 0; dt < 8; dt++) {
            o[dt][0] *= cr0; o[dt][1] *= cr0;
            o[dt][2] *= cr1; o[dt][3] *= cr1;
        }

        // ---- P fragments (A operands), split hi/lo ----
        uint32_t ph[4][4], pl[4][4];
        #pragma unroll
        for (int kt = 0; kt < 4; kt++) {
            split2(s[2*kt][0],   s[2*kt][1],   ph[kt][0], pl[kt][0]);
            split2(s[2*kt][2],   s[2*kt][3],   ph[kt][1], pl[kt][1]);
            split2(s[2*kt+1][0], s[2*kt+1][1], ph[kt][2], pl[kt][2]);
            split2(s[2*kt+1][2], s[2*kt+1][3], ph[kt][3], pl[kt][3]);
        }

        // ---- O += P V (3 split products) ----
        #pragma unroll
        for (int dt = 0; dt < 8; dt++) {
            #pragma unroll
            for (int kt = 0; kt < 4; kt++) {
                uint32_t off = (kt * 16 + t_row) * AT_RW + dt * 16;
                uint32_t vh[2], vl[2];
                ldm_x2t(vh, VHb + off);
                ldm_x2t(vl, VLb + off);
                mma16816(o[dt], ph[kt], vh);
                mma16816(o[dt], ph[kt], vl);
                mma16816(o[dt], pl[kt], vh);
            }
        }

        // ---- prefetch j+2, release stage (j&1) ----
        __syncthreads();
        if (j + 2 <= qi) {
            attn_load_kv(ST + (j & 1) * AT_STAGE, kh_g, kl_g, vh_g, vl_g, base, j + 2, tid);
            CP_COMMIT();
        }
        if (j + 1 <= qi) {
            if (j + 2 <= qi) { CP_WAIT(1); } else { CP_WAIT(0); }
            __syncthreads();
        }
    }

    // ---- epilogue: normalize + split-bf16 store (concat-head layout) ----
    const float inv0 = 1.f / l0, inv1 = 1.f / l1;
    const int b = bh >> 4, h = bh & 15;
    const int row0 = qi * 64 + w * 16 + rloc;
    #pragma unroll
    for (int dt = 0; dt < 8; dt++) {
        int d = dt * 8 + cloc;
        size_t o0 = ((size_t)(b * TT + row0)) * EE + h * HDD + d;
        size_t o1 = o0 + (size_t)8 * EE;
        uint32_t h0, lo0, h1, lo1;
        split2(o[dt][0] * inv0, o[dt][1] * inv0, h0, lo0);
        split2(o[dt][2] * inv1, o[dt][3] * inv1, h1, lo1);
        *(uint32_t*)(ahi + o0) = h0; *(uint32_t*)(alo + o0) = lo0;
        *(uint32_t*)(ahi + o1) = h1; *(uint32_t*)(alo + o1) = lo1;
    }
}

// ---------------------------------------------------------------- launch ----
extern "C" void kernel_launch(void* const* d_in, const int* in_sizes, int n_in,
                              void* d_out, int out_size)
{
    const float* x  = (const float*)d_in[0];
    const float* Wq = (const float*)d_in[1];
    const float* Wk = (const float*)d_in[2];
    const float* Wv = (const float*)d_in[3];
    const float* Wo = (const float*)d_in[4];
    const float* bo = (const float*)d_in[5];
    float* out = (float*)d_out;

    __nv_bfloat16 *qhi,*qlo,*khi,*klo,*vhi,*vlo,*xhi,*xlo,*ahi,*alo;
    __nv_bfloat16 *wqh,*wql,*wkh,*wkl,*wvh,*wvl,*woh,*wol;
    cudaGetSymbolAddress((void**)&qhi, g_qhi); cudaGetSymbolAddress((void**)&qlo, g_qlo);
    cudaGetSymbolAddress((void**)&khi, g_khi); cudaGetSymbolAddress((void**)&klo, g_klo);
    cudaGetSymbolAddress((void**)&vhi, g_vhi); cudaGetSymbolAddress((void**)&vlo, g_vlo);
    cudaGetSymbolAddress((void**)&xhi, g_xhi); cudaGetSymbolAddress((void**)&xlo, g_xlo);
    cudaGetSymbolAddress((void**)&ahi, g_ahi); cudaGetSymbolAddress((void**)&alo, g_alo);
    cudaGetSymbolAddress((void**)&wqh, g_wqhi); cudaGetSymbolAddress((void**)&wql, g_wqlo);
    cudaGetSymbolAddress((void**)&wkh, g_wkhi); cudaGetSymbolAddress((void**)&wkl, g_wklo);
    cudaGetSymbolAddress((void**)&wvh, g_wvhi); cudaGetSymbolAddress((void**)&wvl, g_wvlo);
    cudaGetSymbolAddress((void**)&woh, g_wohi); cudaGetSymbolAddress((void**)&wol, g_wolo);

    const int smem_gemm = 2 * STAGE;
    cudaFuncSetAttribute(gemm_kernel<0>, cudaFuncAttributeMaxDynamicSharedMemorySize, smem_gemm);
    cudaFuncSetAttribute(gemm_kernel<1>, cudaFuncAttributeMaxDynamicSharedMemorySize, smem_gemm);
    cudaFuncSetAttribute(attn_mma_kernel, cudaFuncAttributeMaxDynamicSharedMemorySize, AT_SMEM);

    conv_x_kernel<<<MM * EE / (256 * 8), 256>>>(x, xhi, xlo);
    conv_wT_kernel<<<EE * EE / 256, 256>>>(Wq, wqh, wql);
    conv_wT_kernel<<<EE * EE / 256, 256>>>(Wk, wkh, wkl);
    conv_wT_kernel<<<EE * EE / 256, 256>>>(Wv, wvh, wvl);
    conv_wo_kernel<<<EE * EE / 256, 256>>>(Wo, woh, wol);

    dim3 gg(MM / 128, EE / 128);
    gemm_kernel<0><<<gg, 256, smem_gemm>>>(xhi, xlo, wqh, wql, nullptr, nullptr, qhi, qlo, 0.125f);
    gemm_kernel<0><<<gg, 256, smem_gemm>>>(xhi, xlo, wkh, wkl, nullptr, nullptr, khi, klo, 1.0f);
    gemm_kernel<0><<<gg, 256, smem_gemm>>>(xhi, xlo, wvh, wvl, nullptr, nullptr, vhi, vlo, 1.0f);

    dim3 ga(TT / 64, BB * HH);
    attn_mma_kernel<<<ga, 128, AT_SMEM>>>(qhi, qlo, khi, klo, vhi, vlo, ahi, alo);

    gemm_kernel<1><<<gg, 256, smem_gemm>>>(ahi, alo, woh, wol, bo, out, nullptr, nullptr, 1.0f);
}

// round 5
// speedup vs baseline: 2.7362x; 1.0253x over previous
#include <cuda_runtime.h>
#include <cuda_bf16.h>
#include <cstdint>
#include <math.h>

#define BB 4
#define TT 2048
#define EE 1024
#define HH 16
#define HDD 64
#define MM (BB*TT)

// ---------------------------------------------------------------- scratch ----
__device__ __nv_bfloat16 g_qhi[MM*EE], g_qlo[MM*EE];
__device__ __nv_bfloat16 g_khi[MM*EE], g_klo[MM*EE];
__device__ __nv_bfloat16 g_vhi[MM*EE], g_vlo[MM*EE];
__device__ __nv_bfloat16 g_xhi[MM*EE], g_xlo[MM*EE];
__device__ __nv_bfloat16 g_ahi[MM*EE], g_alo[MM*EE];
__device__ __nv_bfloat16 g_wqhi[EE*EE], g_wqlo[EE*EE];
__device__ __nv_bfloat16 g_wkhi[EE*EE], g_wklo[EE*EE];
__device__ __nv_bfloat16 g_wvhi[EE*EE], g_wvlo[EE*EE];
__device__ __nv_bfloat16 g_wohi[EE*EE], g_wolo[EE*EE];

// ---------------------------------------------------------------- helpers ----
__device__ __forceinline__ uint32_t smem_u32(const void* p) {
    uint32_t a;
    asm("{ .reg .u64 t; cvta.to.shared.u64 t, %1; cvt.u32.u64 %0, t; }" : "=r"(a) : "l"(p));
    return a;
}
__device__ __forceinline__ void cp16(uint32_t saddr, const void* g) {
    asm volatile("cp.async.cg.shared.global [%0], [%1], 16;" :: "r"(saddr), "l"(g));
}
#define CP_COMMIT() asm volatile("cp.async.commit_group;" ::: "memory")
#define CP_WAIT(n)  asm volatile("cp.async.wait_group %0;" :: "n"(n) : "memory")

__device__ __forceinline__ void ldm_x4(uint32_t* r, uint32_t addr) {
    asm volatile("ldmatrix.sync.aligned.m8n8.x4.shared.b16 {%0,%1,%2,%3}, [%4];"
                 : "=r"(r[0]), "=r"(r[1]), "=r"(r[2]), "=r"(r[3]) : "r"(addr));
}
__device__ __forceinline__ void ldm_x4t(uint32_t* r, uint32_t addr) {
    asm volatile("ldmatrix.sync.aligned.m8n8.x4.trans.shared.b16 {%0,%1,%2,%3}, [%4];"
                 : "=r"(r[0]), "=r"(r[1]), "=r"(r[2]), "=r"(r[3]) : "r"(addr));
}
__device__ __forceinline__ void mma16816(float* c, const uint32_t* a, const uint32_t* b) {
    asm volatile("mma.sync.aligned.m16n8k16.row.col.f32.bf16.bf16.f32 "
                 "{%0,%1,%2,%3}, {%4,%5,%6,%7}, {%8,%9}, {%0,%1,%2,%3};"
                 : "+f"(c[0]), "+f"(c[1]), "+f"(c[2]), "+f"(c[3])
                 : "r"(a[0]), "r"(a[1]), "r"(a[2]), "r"(a[3]), "r"(b[0]), "r"(b[1]));
}

__device__ __forceinline__ void split1(float v, ushort& h, ushort& l) {
    __nv_bfloat16 hb = __float2bfloat16(v);
    float rem = v - __bfloat162float(hb);
    __nv_bfloat16 lb = __float2bfloat16(rem);
    h = __bfloat16_as_ushort(hb); l = __bfloat16_as_ushort(lb);
}
__device__ __forceinline__ void split2(float a, float b, uint32_t& hi, uint32_t& lo) {
    ushort h0, l0, h1, l1;
    split1(a, h0, l0); split1(b, h1, l1);
    hi = (uint32_t)h0 | ((uint32_t)h1 << 16);
    lo = (uint32_t)l0 | ((uint32_t)l1 << 16);
}

// ---------------------------------------------------------------- converts --
__global__ __launch_bounds__(256) void conv_x_kernel(const float* __restrict__ x,
        __nv_bfloat16* __restrict__ hi, __nv_bfloat16* __restrict__ lo) {
    size_t i = ((size_t)blockIdx.x * 256 + threadIdx.x) * 8;
    float4 a = *(const float4*)(x + i);
    float4 b = *(const float4*)(x + i + 4);
    float v[8] = {a.x,a.y,a.z,a.w,b.x,b.y,b.z,b.w};
    ushort hs[8], ls[8];
    #pragma unroll
    for (int j = 0; j < 8; j++) split1(v[j], hs[j], ls[j]);
    uint4 ph = make_uint4(hs[0]|(hs[1]<<16), hs[2]|(hs[3]<<16), hs[4]|(hs[5]<<16), hs[6]|(hs[7]<<16));
    uint4 pl = make_uint4(ls[0]|(ls[1]<<16), ls[2]|(ls[3]<<16), ls[4]|(ls[5]<<16), ls[6]|(ls[7]<<16));
    *(uint4*)(hi + i) = ph;
    *(uint4*)(lo + i) = pl;
}

// W[h][e][d] -> WT[h*64+d][e]  via coalesced 32x32 tile transpose
__global__ __launch_bounds__(256) void conv_wT_kernel(const float* __restrict__ W,
        __nv_bfloat16* __restrict__ hi, __nv_bfloat16* __restrict__ lo) {
    __shared__ float ts[32][33];
    const int h  = blockIdx.z;
    const int d0 = blockIdx.y * 32;
    const int e0 = blockIdx.x * 32;
    const int tx = threadIdx.x & 31, ty = threadIdx.x >> 5;
    #pragma unroll
    for (int r = 0; r < 4; r++)
        ts[ty + r*8][tx] = W[((size_t)h * EE + e0 + ty + r*8) * HDD + d0 + tx];
    __syncthreads();
    #pragma unroll
    for (int r = 0; r < 4; r++) {
        float v = ts[tx][ty + r*8];
        ushort hs, ls; split1(v, hs, ls);
        size_t o = (size_t)(h * 64 + d0 + ty + r*8) * EE + e0 + tx;
        hi[o] = __ushort_as_bfloat16(hs);
        lo[o] = __ushort_as_bfloat16(ls);
    }
}

__global__ __launch_bounds__(256) void conv_wo_kernel(const float* __restrict__ W,
        __nv_bfloat16* __restrict__ hi, __nv_bfloat16* __restrict__ lo) {
    int idx = blockIdx.x * 256 + threadIdx.x;
    float v = W[idx];
    ushort hs, ls; split1(v, hs, ls);
    hi[idx] = __ushort_as_bfloat16(hs);
    lo[idx] = __ushort_as_bfloat16(ls);
}

// ------------------------------------------------ HMMA split-bf16 GEMM -------
#define ROWB   80
#define MATB   (128*ROWB)
#define OFF_AH 0
#define OFF_AL (1*MATB)
#define OFF_BH (2*MATB)
#define OFF_BL (3*MATB)
#define STAGE  (4*MATB)

__device__ __forceinline__ void stage_load(uint32_t base,
    const __nv_bfloat16* __restrict__ Ahi, const __nv_bfloat16* __restrict__ Alo,
    const __nv_bfloat16* __restrict__ Bhi, const __nv_bfloat16* __restrict__ Blo,
    int m0, int n0, int k0, int tid)
{
    #pragma unroll
    for (int p = 0; p < 2; p++) {
        int chunk = p * 256 + tid;
        int row = chunk >> 2, ch = chunk & 3;
        uint32_t so = row * ROWB + ch * 16;
        size_t ga = (size_t)(m0 + row) * EE + k0 + ch * 8;
        size_t gb = (size_t)(n0 + row) * EE + k0 + ch * 8;
        cp16(base + OFF_AH + so, Ahi + ga);
        cp16(base + OFF_AL + so, Alo + ga);
        cp16(base + OFF_BH + so, Bhi + gb);
        cp16(base + OFF_BL + so, Blo + gb);
    }
}

template <int MODE>
__global__ __launch_bounds__(256)
void gemm_kernel(const __nv_bfloat16* __restrict__ Ahi, const __nv_bfloat16* __restrict__ Alo,
                 const __nv_bfloat16* __restrict__ Bhi, const __nv_bfloat16* __restrict__ Blo,
                 const float* __restrict__ bias, float* __restrict__ C,
                 __nv_bfloat16* __restrict__ Chi, __nv_bfloat16* __restrict__ Clo,
                 float scale)
{
    extern __shared__ char smem[];
    const int tid = threadIdx.x;
    const int lane = tid & 31, wid = tid >> 5;
    const int wm = wid >> 2, wn = wid & 3;
    const int m0 = blockIdx.x * 128;
    const int n0 = blockIdx.y * 128;
    const uint32_t sb = smem_u32(smem);

    float acc[4][4][4];
    #pragma unroll
    for (int i = 0; i < 4; i++)
        #pragma unroll
        for (int j = 0; j < 4; j++)
            #pragma unroll
            for (int r = 0; r < 4; r++) acc[i][j][r] = 0.f;

    const uint32_t a_row = lane & 15, a_half = lane >> 4;
    const int bm = lane >> 3;                      // 0..3
    const uint32_t b_sub = (bm >> 1) * 8 + (lane & 7);
    const uint32_t b_khalf = (bm & 1) * 8;

    stage_load(sb, Ahi, Alo, Bhi, Blo, m0, n0, 0, tid);
    CP_COMMIT();

    for (int kt = 0; kt < EE / 32; kt++) {
        if (kt + 1 < EE / 32) {
            stage_load(sb + ((kt + 1) & 1) * STAGE, Ahi, Alo, Bhi, Blo,
                       m0, n0, (kt + 1) * 32, tid);
            CP_COMMIT();
            CP_WAIT(1);
        } else {
            CP_WAIT(0);
        }
        __syncthreads();

        const uint32_t st = sb + (kt & 1) * STAGE;
        #pragma unroll
        for (int ks = 0; ks < 2; ks++) {
            uint32_t ah[4][4], al[4][4], bh[2][4], bl[2][4];
            const uint32_t kb  = (ks * 16 + a_half * 8) * 2;
            const uint32_t kbB = (ks * 16 + b_khalf) * 2;
            #pragma unroll
            for (int mi = 0; mi < 4; mi++)
                ldm_x4(ah[mi], st + OFF_AH + (wm * 64 + mi * 16 + a_row) * ROWB + kb);
            #pragma unroll
            for (int np = 0; np < 2; np++)
                ldm_x4(bh[np], st + OFF_BH + (wn * 32 + np * 16 + b_sub) * ROWB + kbB);
            #pragma unroll
            for (int mi = 0; mi < 4; mi++)
                #pragma unroll
                for (int np = 0; np < 2; np++) {
                    mma16816(acc[mi][np*2],   ah[mi], &bh[np][0]);
                    mma16816(acc[mi][np*2+1], ah[mi], &bh[np][2]);
                }
            #pragma unroll
            for (int np = 0; np < 2; np++)
                ldm_x4(bl[np], st + OFF_BL + (wn * 32 + np * 16 + b_sub) * ROWB + kbB);
            #pragma unroll
            for (int mi = 0; mi < 4; mi++)
                #pragma unroll
                for (int np = 0; np < 2; np++) {
                    mma16816(acc[mi][np*2],   ah[mi], &bl[np][0]);
                    mma16816(acc[mi][np*2+1], ah[mi], &bl[np][2]);
                }
            #pragma unroll
            for (int mi = 0; mi < 4; mi++)
                ldm_x4(al[mi], st + OFF_AL + (wm * 64 + mi * 16 + a_row) * ROWB + kb);
            #pragma unroll
            for (int mi = 0; mi < 4; mi++)
                #pragma unroll
                for (int np = 0; np < 2; np++) {
                    mma16816(acc[mi][np*2],   al[mi], &bh[np][0]);
                    mma16816(acc[mi][np*2+1], al[mi], &bh[np][2]);
                }
        }
        __syncthreads();
    }

    const int rbase = lane >> 2;
    const int cbase = (lane & 3) * 2;
    #pragma unroll
    for (int mi = 0; mi < 4; mi++) {
        #pragma unroll
        for (int ni = 0; ni < 4; ni++) {
            int mrow = m0 + wm * 64 + mi * 16 + rbase;
            int ncol = n0 + wn * 32 + ni * 8 + cbase;
            if (MODE == 0) {
                int head = ncol >> 6, d = ncol & 63;
                int b = mrow >> 11, t = mrow & 2047;
                size_t o0 = ((size_t)(b * HH + head) * TT + t) * HDD + d;
                size_t o1 = o0 + 8 * HDD;
                uint32_t h0, l0, h1, l1;
                split2(acc[mi][ni][0] * scale, acc[mi][ni][1] * scale, h0, l0);
                split2(acc[mi][ni][2] * scale, acc[mi][ni][3] * scale, h1, l1);
                *(uint32_t*)(Chi + o0) = h0; *(uint32_t*)(Clo + o0) = l0;
                *(uint32_t*)(Chi + o1) = h1; *(uint32_t*)(Clo + o1) = l1;
            } else {
                float2 bv = *(const float2*)(bias + ncol);
                float* dst = C + (size_t)mrow * EE + ncol;
                *(float2*)dst = make_float2(acc[mi][ni][0] + bv.x, acc[mi][ni][1] + bv.y);
                *(float2*)(dst + 8 * EE) = make_float2(acc[mi][ni][2] + bv.x,
                                                       acc[mi][ni][3] + bv.y);
            }
        }
    }
}

// ---------------- HMMA flash attention: 128 q-rows, 256 thr, 3-stage pipe ----
#define AT_RW    144
#define AT_MAT   (64*AT_RW)            // 9216  (one 64-row matrix)
#define AT_QMAT  (128*AT_RW)           // 18432 (one 128-row matrix)
#define AT_ST    (2*AT_QMAT)           // 36864 (QH+QL)
#define AT_STAGE (4*AT_MAT)            // 36864 per KV stage
#define AT_SMEM  (AT_ST + 3*AT_STAGE)  // 147456

__device__ __forceinline__ void attn_load_kv(uint32_t dst,
    const __nv_bfloat16* kh, const __nv_bfloat16* kl,
    const __nv_bfloat16* vh, const __nv_bfloat16* vl,
    size_t base, int j, int tid)
{
    const __nv_bfloat16* mats[4] = {kh, kl, vh, vl};
    #pragma unroll
    for (int p = 0; p < 8; p++) {
        int idx = p * 256 + tid;
        int mat = idx >> 9, rem = idx & 511;
        int row = rem >> 3, ch = rem & 7;
        cp16(dst + mat * AT_MAT + row * AT_RW + ch * 16,
             mats[mat] + base + (size_t)(j * 64 + row) * HDD + ch * 8);
    }
}

__global__ __launch_bounds__(256)
void attn_mma_kernel(const __nv_bfloat16* __restrict__ qh_g, const __nv_bfloat16* __restrict__ ql_g,
                     const __nv_bfloat16* __restrict__ kh_g, const __nv_bfloat16* __restrict__ kl_g,
                     const __nv_bfloat16* __restrict__ vh_g, const __nv_bfloat16* __restrict__ vl_g,
                     __nv_bfloat16* __restrict__ ahi, __nv_bfloat16* __restrict__ alo)
{
    extern __shared__ char smem[];
    const int tid = threadIdx.x, lane = tid & 31, w = tid >> 5;
    const int qb = (gridDim.x - 1) - blockIdx.x;       // 0..15, longest first
    const int bh = blockIdx.y;
    const int jmax = 2 * qb + 1;
    const size_t base = (size_t)bh * TT * HDD;
    const uint32_t sb = smem_u32(smem);
    const uint32_t QH = sb, QL = QH + AT_QMAT;
    const uint32_t ST = sb + AT_ST;

    // Q tile + KV stage 0 (group 0)
    {
        const __nv_bfloat16* qm[2] = {qh_g, ql_g};
        #pragma unroll
        for (int p = 0; p < 8; p++) {
            int idx = p * 256 + tid;
            int mat = idx >> 10, rem = idx & 1023;
            int row = rem >> 3, ch = rem & 7;
            cp16(QH + mat * AT_QMAT + row * AT_RW + ch * 16,
                 qm[mat] + base + (size_t)(qb * 128 + row) * HDD + ch * 8);
        }
        attn_load_kv(ST, kh_g, kl_g, vh_g, vl_g, base, 0, tid);
        CP_COMMIT();
    }
    attn_load_kv(ST + AT_STAGE, kh_g, kl_g, vh_g, vl_g, base, 1, tid);
    CP_COMMIT();
    if (jmax >= 2) {
        attn_load_kv(ST + 2 * AT_STAGE, kh_g, kl_g, vh_g, vl_g, base, 2, tid);
        CP_COMMIT();
        CP_WAIT(2);
    } else {
        CP_WAIT(1);
    }
    __syncthreads();

    uint32_t qh[4][4], ql[4][4];
    {
        const uint32_t a_row = lane & 15, a_half = lane >> 4;
        #pragma unroll
        for (int ks = 0; ks < 4; ks++) {
            uint32_t off = (w * 16 + a_row) * AT_RW + (ks * 16 + a_half * 8) * 2;
            ldm_x4(qh[ks], QH + off);
            ldm_x4(ql[ks], QL + off);
        }
    }

    float o[8][4];
    #pragma unroll
    for (int dt = 0; dt < 8; dt++)
        #pragma unroll
        for (int r = 0; r < 4; r++) o[dt][r] = 0.f;
    float m0 = -1e30f, m1 = -1e30f, l0 = 0.f, l1 = 0.f;

    const int bm = lane >> 3;
    const uint32_t b_sub = (bm >> 1) * 8 + (lane & 7);
    const uint32_t b_khalf = (bm & 1) * 8;
    const uint32_t t_row = lane & 15, t_col = lane >> 4;
    const int rloc = lane >> 2;
    const int cloc = (lane & 3) * 2;

    for (int j = 0; j <= jmax; j++) {
        const uint32_t KHb = ST + (j % 3) * AT_STAGE;
        const uint32_t KLb = KHb + AT_MAT, VHb = KHb + 2*AT_MAT, VLb = KHb + 3*AT_MAT;

        // ---- S = Q K^T ----
        float s[8][4];
        #pragma unroll
        for (int np = 0; np < 4; np++) {
            s[2*np][0]=s[2*np][1]=s[2*np][2]=s[2*np][3]=0.f;
            s[2*np+1][0]=s[2*np+1][1]=s[2*np+1][2]=s[2*np+1][3]=0.f;
            #pragma unroll
            for (int ks = 0; ks < 4; ks++) {
                uint32_t off = (np * 16 + b_sub) * AT_RW + (ks * 16 + b_khalf) * 2;
                uint32_t kh4[4], kl4[4];
                ldm_x4(kh4, KHb + off);
                ldm_x4(kl4, KLb + off);
                mma16816(s[2*np],   qh[ks], &kh4[0]);
                mma16816(s[2*np],   qh[ks], &kl4[0]);
                mma16816(s[2*np],   ql[ks], &kh4[0]);
                mma16816(s[2*np+1], qh[ks], &kh4[2]);
                mma16816(s[2*np+1], qh[ks], &kl4[2]);
                mma16816(s[2*np+1], ql[ks], &kh4[2]);
            }
        }

        // ---- causal mask (two diagonal tiles) ----
        if (j >= 2 * qb) {
            int r0g = qb * 128 + w * 16 + rloc;
            int c0g = j * 64;
            #pragma unroll
            for (int nt = 0; nt < 8; nt++) {
                int col = c0g + nt * 8 + cloc;
                if (col     > r0g)     s[nt][0] = -1e30f;
                if (col + 1 > r0g)     s[nt][1] = -1e30f;
                if (col     > r0g + 8) s[nt][2] = -1e30f;
                if (col + 1 > r0g + 8) s[nt][3] = -1e30f;
            }
        }

        // ---- online softmax ----
        float mx0 = -1e30f, mx1 = -1e30f;
        #pragma unroll
        for (int nt = 0; nt < 8; nt++) {
            mx0 = fmaxf(mx0, fmaxf(s[nt][0], s[nt][1]));
            mx1 = fmaxf(mx1, fmaxf(s[nt][2], s[nt][3]));
        }
        mx0 = fmaxf(mx0, __shfl_xor_sync(0xffffffffu, mx0, 1));
        mx0 = fmaxf(mx0, __shfl_xor_sync(0xffffffffu, mx0, 2));
        mx1 = fmaxf(mx1, __shfl_xor_sync(0xffffffffu, mx1, 1));
        mx1 = fmaxf(mx1, __shfl_xor_sync(0xffffffffu, mx1, 2));
        float mn0 = fmaxf(m0, mx0), mn1 = fmaxf(m1, mx1);
        float cr0 = __expf(m0 - mn0), cr1 = __expf(m1 - mn1);
        float ls0 = 0.f, ls1 = 0.f;
        #pragma unroll
        for (int nt = 0; nt < 8; nt++) {
            s[nt][0] = __expf(s[nt][0] - mn0); ls0 += s[nt][0];
            s[nt][1] = __expf(s[nt][1] - mn0); ls0 += s[nt][1];
            s[nt][2] = __expf(s[nt][2] - mn1); ls1 += s[nt][2];
            s[nt][3] = __expf(s[nt][3] - mn1); ls1 += s[nt][3];
        }
        ls0 += __shfl_xor_sync(0xffffffffu, ls0, 1);
        ls0 += __shfl_xor_sync(0xffffffffu, ls0, 2);
        ls1 += __shfl_xor_sync(0xffffffffu, ls1, 1);
        ls1 += __shfl_xor_sync(0xffffffffu, ls1, 2);
        l0 = l0 * cr0 + ls0;  m0 = mn0;
        l1 = l1 * cr1 + ls1;  m1 = mn1;
        #pragma unroll
        for (int dt = 0; dt < 8; dt++) {
            o[dt][0] *= cr0; o[dt][1] *= cr0;
            o[dt][2] *= cr1; o[dt][3] *= cr1;
        }

        // ---- P fragments ----
        uint32_t ph[4][4], pl[4][4];
        #pragma unroll
        for (int kt = 0; kt < 4; kt++) {
            split2(s[2*kt][0],   s[2*kt][1],   ph[kt][0], pl[kt][0]);
            split2(s[2*kt][2],   s[2*kt][3],   ph[kt][1], pl[kt][1]);
            split2(s[2*kt+1][0], s[2*kt+1][1], ph[kt][2], pl[kt][2]);
            split2(s[2*kt+1][2], s[2*kt+1][3], ph[kt][3], pl[kt][3]);
        }

        // ---- O += P V ----
        #pragma unroll
        for (int dp = 0; dp < 4; dp++) {
            #pragma unroll
            for (int kt = 0; kt < 4; kt++) {
                uint32_t off = (kt * 16 + t_row) * AT_RW + (dp * 2 + t_col) * 16;
                uint32_t vh4[4], vl4[4];
                ldm_x4t(vh4, VHb + off);
                ldm_x4t(vl4, VLb + off);
                mma16816(o[dp*2],   ph[kt], &vh4[0]);
                mma16816(o[dp*2],   ph[kt], &vl4[0]);
                mma16816(o[dp*2],   pl[kt], &vh4[0]);
                mma16816(o[dp*2+1], ph[kt], &vh4[2]);
                mma16816(o[dp*2+1], ph[kt], &vl4[2]);
                mma16816(o[dp*2+1], pl[kt], &vh4[2]);
            }
        }

        // ---- pipeline: load j+3 into stage (j%3) ----
        __syncthreads();
        if (j + 3 <= jmax) {
            attn_load_kv(ST + (j % 3) * AT_STAGE, kh_g, kl_g, vh_g, vl_g, base, j + 3, tid);
            CP_COMMIT();
        }
        if (j + 1 <= jmax) {
            if (j + 3 <= jmax)      { CP_WAIT(2); }
            else if (j + 2 <= jmax) { CP_WAIT(1); }
            else                    { CP_WAIT(0); }
            __syncthreads();
        }
    }

    // ---- epilogue ----
    const float inv0 = 1.f / l0, inv1 = 1.f / l1;
    const int b = bh >> 4, h = bh & 15;
    const int row0 = qb * 128 + w * 16 + rloc;
    #pragma unroll
    for (int dt = 0; dt < 8; dt++) {
        int d = dt * 8 + cloc;
        size_t o0 = ((size_t)(b * TT + row0)) * EE + h * HDD + d;
        size_t o1 = o0 + (size_t)8 * EE;
        uint32_t h0, lo0, h1, lo1;
        split2(o[dt][0] * inv0, o[dt][1] * inv0, h0, lo0);
        split2(o[dt][2] * inv1, o[dt][3] * inv1, h1, lo1);
        *(uint32_t*)(ahi + o0) = h0; *(uint32_t*)(alo + o0) = lo0;
        *(uint32_t*)(ahi + o1) = h1; *(uint32_t*)(alo + o1) = lo1;
    }
}

// ---------------------------------------------------------------- launch ----
extern "C" void kernel_launch(void* const* d_in, const int* in_sizes, int n_in,
                              void* d_out, int out_size)
{
    const float* x  = (const float*)d_in[0];
    const float* Wq = (const float*)d_in[1];
    const float* Wk = (const float*)d_in[2];
    const float* Wv = (const float*)d_in[3];
    const float* Wo = (const float*)d_in[4];
    const float* bo = (const float*)d_in[5];
    float* out = (float*)d_out;

    __nv_bfloat16 *qhi,*qlo,*khi,*klo,*vhi,*vlo,*xhi,*xlo,*ahi,*alo;
    __nv_bfloat16 *wqh,*wql,*wkh,*wkl,*wvh,*wvl,*woh,*wol;
    cudaGetSymbolAddress((void**)&qhi, g_qhi); cudaGetSymbolAddress((void**)&qlo, g_qlo);
    cudaGetSymbolAddress((void**)&khi, g_khi); cudaGetSymbolAddress((void**)&klo, g_klo);
    cudaGetSymbolAddress((void**)&vhi, g_vhi); cudaGetSymbolAddress((void**)&vlo, g_vlo);
    cudaGetSymbolAddress((void**)&xhi, g_xhi); cudaGetSymbolAddress((void**)&xlo, g_xlo);
    cudaGetSymbolAddress((void**)&ahi, g_ahi); cudaGetSymbolAddress((void**)&alo, g_alo);
    cudaGetSymbolAddress((void**)&wqh, g_wqhi); cudaGetSymbolAddress((void**)&wql, g_wqlo);
    cudaGetSymbolAddress((void**)&wkh, g_wkhi); cudaGetSymbolAddress((void**)&wkl, g_wklo);
    cudaGetSymbolAddress((void**)&wvh, g_wvhi); cudaGetSymbolAddress((void**)&wvl, g_wvlo);
    cudaGetSymbolAddress((void**)&woh, g_wohi); cudaGetSymbolAddress((void**)&wol, g_wolo);

    const int smem_gemm = 2 * STAGE;
    cudaFuncSetAttribute(gemm_kernel<0>, cudaFuncAttributeMaxDynamicSharedMemorySize, smem_gemm);
    cudaFuncSetAttribute(gemm_kernel<1>, cudaFuncAttributeMaxDynamicSharedMemorySize, smem_gemm);
    cudaFuncSetAttribute(attn_mma_kernel, cudaFuncAttributeMaxDynamicSharedMemorySize, AT_SMEM);

    conv_x_kernel<<<MM * EE / (256 * 8), 256>>>(x, xhi, xlo);
    dim3 gw(EE / 32, HDD / 32, HH);
    conv_wT_kernel<<<gw, 256>>>(Wq, wqh, wql);
    conv_wT_kernel<<<gw, 256>>>(Wk, wkh, wkl);
    conv_wT_kernel<<<gw, 256>>>(Wv, wvh, wvl);
    conv_wo_kernel<<<EE * EE / 256, 256>>>(Wo, woh, wol);

    dim3 gg(MM / 128, EE / 128);
    gemm_kernel<0><<<gg, 256, smem_gemm>>>(xhi, xlo, wqh, wql, nullptr, nullptr, qhi, qlo, 0.125f);
    gemm_kernel<0><<<gg, 256, smem_gemm>>>(xhi, xlo, wkh, wkl, nullptr, nullptr, khi, klo, 1.0f);
    gemm_kernel<0><<<gg, 256, smem_gemm>>>(xhi, xlo, wvh, wvl, nullptr, nullptr, vhi, vlo, 1.0f);

    dim3 ga(TT / 128, BB * HH);
    attn_mma_kernel<<<ga, 256, AT_SMEM>>>(qhi, qlo, khi, klo, vhi, vlo, ahi, alo);

    gemm_kernel<1><<<gg, 256, smem_gemm>>>(ahi, alo, woh, wol, bo, out, nullptr, nullptr, 1.0f);
}

// round 6
// speedup vs baseline: 3.6051x; 1.3175x over previous
#include <cuda_runtime.h>
#include <cuda_fp16.h>
#include <cstdint>
#include <math.h>

#define BB 4
#define TT 2048
#define EE 1024
#define HH 16
#define HDD 64
#define MM (BB*TT)

// ---------------------------------------------------------------- scratch ----
__device__ __half g_qhi[MM*EE], g_qlo[MM*EE];      // (b,h,t,d), pre-scaled by 1/8
__device__ __half g_khi[MM*EE];                    // K kept fp16-only (2-product S)
__device__ __half g_vhi[MM*EE], g_vlo[MM*EE];
__device__ __half g_xhi[MM*EE], g_xlo[MM*EE];
__device__ __half g_ahi[MM*EE], g_alo[MM*EE];
__device__ __half g_wqhi[EE*EE], g_wqlo[EE*EE];    // transposed: [h*64+d][e]
__device__ __half g_wkhi[EE*EE], g_wklo[EE*EE];
__device__ __half g_wvhi[EE*EE], g_wvlo[EE*EE];
__device__ __half g_wohi[EE*EE], g_wolo[EE*EE];    // natural: [n][k]

// ---------------------------------------------------------------- helpers ----
__device__ __forceinline__ uint32_t smem_u32(const void* p) {
    uint32_t a;
    asm("{ .reg .u64 t; cvta.to.shared.u64 t, %1; cvt.u32.u64 %0, t; }" : "=r"(a) : "l"(p));
    return a;
}
__device__ __forceinline__ void cp16(uint32_t saddr, const void* g) {
    asm volatile("cp.async.cg.shared.global [%0], [%1], 16;" :: "r"(saddr), "l"(g));
}
#define CP_COMMIT() asm volatile("cp.async.commit_group;" ::: "memory")
#define CP_WAIT(n)  asm volatile("cp.async.wait_group %0;" :: "n"(n) : "memory")

__device__ __forceinline__ void ldm_x4(uint32_t* r, uint32_t addr) {
    asm volatile("ldmatrix.sync.aligned.m8n8.x4.shared.b16 {%0,%1,%2,%3}, [%4];"
                 : "=r"(r[0]), "=r"(r[1]), "=r"(r[2]), "=r"(r[3]) : "r"(addr));
}
__device__ __forceinline__ void ldm_x4t(uint32_t* r, uint32_t addr) {
    asm volatile("ldmatrix.sync.aligned.m8n8.x4.trans.shared.b16 {%0,%1,%2,%3}, [%4];"
                 : "=r"(r[0]), "=r"(r[1]), "=r"(r[2]), "=r"(r[3]) : "r"(addr));
}
__device__ __forceinline__ void mma16816(float* c, const uint32_t* a, const uint32_t* b) {
    asm volatile("mma.sync.aligned.m16n8k16.row.col.f32.f16.f16.f32 "
                 "{%0,%1,%2,%3}, {%4,%5,%6,%7}, {%8,%9}, {%0,%1,%2,%3};"
                 : "+f"(c[0]), "+f"(c[1]), "+f"(c[2]), "+f"(c[3])
                 : "r"(a[0]), "r"(a[1]), "r"(a[2]), "r"(a[3]), "r"(b[0]), "r"(b[1]));
}

__device__ __forceinline__ void split1(float v, ushort& h, ushort& l) {
    __half hb = __float2half_rn(v);
    float rem = v - __half2float(hb);
    __half lb = __float2half_rn(rem);
    h = __half_as_ushort(hb); l = __half_as_ushort(lb);
}
__device__ __forceinline__ void split2(float a, float b, uint32_t& hi, uint32_t& lo) {
    ushort h0, l0, h1, l1;
    split1(a, h0, l0); split1(b, h1, l1);
    hi = (uint32_t)h0 | ((uint32_t)h1 << 16);
    lo = (uint32_t)l0 | ((uint32_t)l1 << 16);
}
__device__ __forceinline__ uint32_t pack2h(float a, float b) {
    __half2 h = __floats2half2_rn(a, b);
    return *(uint32_t*)&h;
}

// ---------------------------------------------------------------- converts --
__global__ __launch_bounds__(256) void conv_x_kernel(const float* __restrict__ x) {
    size_t i = ((size_t)blockIdx.x * 256 + threadIdx.x) * 8;
    float4 a = *(const float4*)(x + i);
    float4 b = *(const float4*)(x + i + 4);
    float v[8] = {a.x,a.y,a.z,a.w,b.x,b.y,b.z,b.w};
    ushort hs[8], ls[8];
    #pragma unroll
    for (int j = 0; j < 8; j++) split1(v[j], hs[j], ls[j]);
    uint4 ph = make_uint4(hs[0]|(hs[1]<<16), hs[2]|(hs[3]<<16), hs[4]|(hs[5]<<16), hs[6]|(hs[7]<<16));
    uint4 pl = make_uint4(ls[0]|(ls[1]<<16), ls[2]|(ls[3]<<16), ls[4]|(ls[5]<<16), ls[6]|(ls[7]<<16));
    *(uint4*)(g_xhi + i) = ph;
    *(uint4*)(g_xlo + i) = pl;
}

// W[h][e][d] -> WT[h*64+d][e]; blockIdx.z = wsel*16 + h
__global__ __launch_bounds__(256) void conv_w_kernel(const float* __restrict__ Wq,
        const float* __restrict__ Wk, const float* __restrict__ Wv) {
    __shared__ float ts[32][33];
    const int wsel = blockIdx.z >> 4;
    const int h  = blockIdx.z & 15;
    const int d0 = blockIdx.y * 32;
    const int e0 = blockIdx.x * 32;
    const float* W = (wsel == 0) ? Wq : (wsel == 1) ? Wk : Wv;
    __half* hi = (wsel == 0) ? g_wqhi : (wsel == 1) ? g_wkhi : g_wvhi;
    __half* lo = (wsel == 0) ? g_wqlo : (wsel == 1) ? g_wklo : g_wvlo;
    const int tx = threadIdx.x & 31, ty = threadIdx.x >> 5;
    #pragma unroll
    for (int r = 0; r < 4; r++)
        ts[ty + r*8][tx] = W[((size_t)h * EE + e0 + ty + r*8) * HDD + d0 + tx];
    __syncthreads();
    #pragma unroll
    for (int r = 0; r < 4; r++) {
        float v = ts[tx][ty + r*8];
        ushort hs, ls; split1(v, hs, ls);
        size_t o = (size_t)(h * 64 + d0 + ty + r*8) * EE + e0 + tx;
        hi[o] = __ushort_as_half(hs);
        lo[o] = __ushort_as_half(ls);
    }
}

__global__ __launch_bounds__(256) void conv_wo_kernel(const float* __restrict__ W) {
    int idx = blockIdx.x * 256 + threadIdx.x;
    float v = W[idx];
    ushort hs, ls; split1(v, hs, ls);
    g_wohi[idx] = __ushort_as_half(hs);
    g_wolo[idx] = __ushort_as_half(ls);
}

// ------------------------------------------------ HMMA split-fp16 GEMM core --
#define ROWB   80
#define MATB   (128*ROWB)
#define OFF_AH 0
#define OFF_AL (1*MATB)
#define OFF_BH (2*MATB)
#define OFF_BL (3*MATB)
#define STAGE  (4*MATB)

__device__ __forceinline__ void stage_load(uint32_t base,
    const __half* __restrict__ Ahi, const __half* __restrict__ Alo,
    const __half* __restrict__ Bhi, const __half* __restrict__ Blo,
    int m0, int n0, int k0, int tid)
{
    #pragma unroll
    for (int p = 0; p < 2; p++) {
        int chunk = p * 256 + tid;
        int row = chunk >> 2, ch = chunk & 3;
        uint32_t so = row * ROWB + ch * 16;
        size_t ga = (size_t)(m0 + row) * EE + k0 + ch * 8;
        size_t gb = (size_t)(n0 + row) * EE + k0 + ch * 8;
        cp16(base + OFF_AH + so, Ahi + ga);
        cp16(base + OFF_AL + so, Alo + ga);
        cp16(base + OFF_BH + so, Bhi + gb);
        cp16(base + OFF_BL + so, Blo + gb);
    }
}

__device__ __forceinline__ void gemm_core(
    const __half* __restrict__ Ahi, const __half* __restrict__ Alo,
    const __half* __restrict__ Bhi, const __half* __restrict__ Blo,
    int m0, int n0, float acc[4][4][4], char* smem)
{
    const int tid = threadIdx.x;
    const int lane = tid & 31, wid = tid >> 5;
    const int wm = wid >> 2, wn = wid & 3;
    const uint32_t sb = smem_u32(smem);

    const uint32_t a_row = lane & 15, a_half = lane >> 4;
    const int bm = lane >> 3;
    const uint32_t b_sub = (bm >> 1) * 8 + (lane & 7);
    const uint32_t b_khalf = (bm & 1) * 8;

    stage_load(sb, Ahi, Alo, Bhi, Blo, m0, n0, 0, tid);
    CP_COMMIT();

    for (int kt = 0; kt < EE / 32; kt++) {
        if (kt + 1 < EE / 32) {
            stage_load(sb + ((kt + 1) & 1) * STAGE, Ahi, Alo, Bhi, Blo,
                       m0, n0, (kt + 1) * 32, tid);
            CP_COMMIT();
            CP_WAIT(1);
        } else {
            CP_WAIT(0);
        }
        __syncthreads();

        const uint32_t st = sb + (kt & 1) * STAGE;
        #pragma unroll
        for (int ks = 0; ks < 2; ks++) {
            uint32_t ah[4][4], al[4][4], bh[2][4], bl[2][4];
            const uint32_t kb  = (ks * 16 + a_half * 8) * 2;
            const uint32_t kbB = (ks * 16 + b_khalf) * 2;
            #pragma unroll
            for (int mi = 0; mi < 4; mi++)
                ldm_x4(ah[mi], st + OFF_AH + (wm * 64 + mi * 16 + a_row) * ROWB + kb);
            #pragma unroll
            for (int np = 0; np < 2; np++)
                ldm_x4(bh[np], st + OFF_BH + (wn * 32 + np * 16 + b_sub) * ROWB + kbB);
            #pragma unroll
            for (int mi = 0; mi < 4; mi++)
                #pragma unroll
                for (int np = 0; np < 2; np++) {
                    mma16816(acc[mi][np*2],   ah[mi], &bh[np][0]);
                    mma16816(acc[mi][np*2+1], ah[mi], &bh[np][2]);
                }
            #pragma unroll
            for (int np = 0; np < 2; np++)
                ldm_x4(bl[np], st + OFF_BL + (wn * 32 + np * 16 + b_sub) * ROWB + kbB);
            #pragma unroll
            for (int mi = 0; mi < 4; mi++)
                #pragma unroll
                for (int np = 0; np < 2; np++) {
                    mma16816(acc[mi][np*2],   ah[mi], &bl[np][0]);
                    mma16816(acc[mi][np*2+1], ah[mi], &bl[np][2]);
                }
            #pragma unroll
            for (int mi = 0; mi < 4; mi++)
                ldm_x4(al[mi], st + OFF_AL + (wm * 64 + mi * 16 + a_row) * ROWB + kb);
            #pragma unroll
            for (int mi = 0; mi < 4; mi++)
                #pragma unroll
                for (int np = 0; np < 2; np++) {
                    mma16816(acc[mi][np*2],   al[mi], &bh[np][0]);
                    mma16816(acc[mi][np*2+1], al[mi], &bh[np][2]);
                }
        }
        __syncthreads();
    }
}

// QKV projections in one launch: blockIdx.z selects q/k/v.
__global__ __launch_bounds__(256)
void gemm_qkv_kernel()
{
    extern __shared__ char smem[];
    const int z = blockIdx.z;
    const int m0 = blockIdx.x * 128;
    const int n0 = blockIdx.y * 128;

    const __half* Bh = (z == 0) ? g_wqhi : (z == 1) ? g_wkhi : g_wvhi;
    const __half* Bl = (z == 0) ? g_wqlo : (z == 1) ? g_wklo : g_wvlo;

    float acc[4][4][4];
    #pragma unroll
    for (int i = 0; i < 4; i++)
        #pragma unroll
        for (int j = 0; j < 4; j++)
            #pragma unroll
            for (int r = 0; r < 4; r++) acc[i][j][r] = 0.f;

    gemm_core(g_xhi, g_xlo, Bh, Bl, m0, n0, acc, smem);

    __half* Chi = (z == 0) ? g_qhi : (z == 1) ? g_khi : g_vhi;
    __half* Clo = (z == 0) ? g_qlo : g_vlo;      // unused for z==1
    const float scale = (z == 0) ? 0.125f : 1.0f;
    const bool wlo = (z != 1);

    const int lane = threadIdx.x & 31, wid = threadIdx.x >> 5;
    const int wm = wid >> 2, wn = wid & 3;
    const int rbase = lane >> 2;
    const int cbase = (lane & 3) * 2;
    #pragma unroll
    for (int mi = 0; mi < 4; mi++) {
        #pragma unroll
        for (int ni = 0; ni < 4; ni++) {
            int mrow = m0 + wm * 64 + mi * 16 + rbase;
            int ncol = n0 + wn * 32 + ni * 8 + cbase;
            int head = ncol >> 6, d = ncol & 63;
            int b = mrow >> 11, t = mrow & 2047;
            size_t o0 = ((size_t)(b * HH + head) * TT + t) * HDD + d;
            size_t o1 = o0 + 8 * HDD;
            uint32_t h0, l0, h1, l1;
            split2(acc[mi][ni][0] * scale, acc[mi][ni][1] * scale, h0, l0);
            split2(acc[mi][ni][2] * scale, acc[mi][ni][3] * scale, h1, l1);
            *(uint32_t*)(Chi + o0) = h0;
            *(uint32_t*)(Chi + o1) = h1;
            if (wlo) {
                *(uint32_t*)(Clo + o0) = l0;
                *(uint32_t*)(Clo + o1) = l1;
            }
        }
    }
}

// Output projection: out = att @ Wo^T + bo (fp32 out)
__global__ __launch_bounds__(256)
void gemm_o_kernel(const float* __restrict__ bias, float* __restrict__ C)
{
    extern __shared__ char smem[];
    const int m0 = blockIdx.x * 128;
    const int n0 = blockIdx.y * 128;

    float acc[4][4][4];
    #pragma unroll
    for (int i = 0; i < 4; i++)
        #pragma unroll
        for (int j = 0; j < 4; j++)
            #pragma unroll
            for (int r = 0; r < 4; r++) acc[i][j][r] = 0.f;

    gemm_core(g_ahi, g_alo, g_wohi, g_wolo, m0, n0, acc, smem);

    const int lane = threadIdx.x & 31, wid = threadIdx.x >> 5;
    const int wm = wid >> 2, wn = wid & 3;
    const int rbase = lane >> 2;
    const int cbase = (lane & 3) * 2;
    #pragma unroll
    for (int mi = 0; mi < 4; mi++) {
        #pragma unroll
        for (int ni = 0; ni < 4; ni++) {
            int mrow = m0 + wm * 64 + mi * 16 + rbase;
            int ncol = n0 + wn * 32 + ni * 8 + cbase;
            float2 bv = *(const float2*)(bias + ncol);
            float* dst = C + (size_t)mrow * EE + ncol;
            *(float2*)dst = make_float2(acc[mi][ni][0] + bv.x, acc[mi][ni][1] + bv.y);
            *(float2*)(dst + 8 * EE) = make_float2(acc[mi][ni][2] + bv.x,
                                                   acc[mi][ni][3] + bv.y);
        }
    }
}

// ---------------- HMMA flash attention: fp16, 2-product S and PV -------------
// CTA: 128 q-rows. Stage: {Kh, Vh, Vl}. 3-stage cp.async ring.
#define AT_RW    144
#define AT_MAT   (64*AT_RW)            // 9216
#define AT_QMAT  (128*AT_RW)           // 18432
#define AT_ST    (2*AT_QMAT)           // 36864 (QH+QL)
#define AT_STAGE (3*AT_MAT)            // 27648
#define AT_SMEM  (AT_ST + 3*AT_STAGE)  // 119808

__device__ __forceinline__ void attn_load_kv(uint32_t dst, size_t base, int j, int tid)
{
    const __half* mats[3] = {g_khi, g_vhi, g_vlo};
    #pragma unroll
    for (int p = 0; p < 6; p++) {
        int idx = p * 256 + tid;          // 0..1535
        int mat = idx >> 9, rem = idx & 511;
        int row = rem >> 3, ch = rem & 7;
        cp16(dst + mat * AT_MAT + row * AT_RW + ch * 16,
             mats[mat] + base + (size_t)(j * 64 + row) * HDD + ch * 8);
    }
}

__global__ __launch_bounds__(256)
void attn_mma_kernel()
{
    extern __shared__ char smem[];
    const int tid = threadIdx.x, lane = tid & 31, w = tid >> 5;
    const int qb = (gridDim.x - 1) - blockIdx.x;
    const int bh = blockIdx.y;
    const int jmax = 2 * qb + 1;
    const size_t base = (size_t)bh * TT * HDD;
    const uint32_t sb = smem_u32(smem);
    const uint32_t QH = sb, QL = QH + AT_QMAT;
    const uint32_t ST = sb + AT_ST;

    // Q tile + KV stage 0
    {
        const __half* qm[2] = {g_qhi, g_qlo};
        #pragma unroll
        for (int p = 0; p < 8; p++) {
            int idx = p * 256 + tid;
            int mat = idx >> 10, rem = idx & 1023;
            int row = rem >> 3, ch = rem & 7;
            cp16(QH + mat * AT_QMAT + row * AT_RW + ch * 16,
                 qm[mat] + base + (size_t)(qb * 128 + row) * HDD + ch * 8);
        }
        attn_load_kv(ST, base, 0, tid);
        CP_COMMIT();
    }
    attn_load_kv(ST + AT_STAGE, base, 1, tid);
    CP_COMMIT();
    if (jmax >= 2) {
        attn_load_kv(ST + 2 * AT_STAGE, base, 2, tid);
        CP_COMMIT();
        CP_WAIT(2);
    } else {
        CP_WAIT(1);
    }
    __syncthreads();

    uint32_t qh[4][4], ql[4][4];
    {
        const uint32_t a_row = lane & 15, a_half = lane >> 4;
        #pragma unroll
        for (int ks = 0; ks < 4; ks++) {
            uint32_t off = (w * 16 + a_row) * AT_RW + (ks * 16 + a_half * 8) * 2;
            ldm_x4(qh[ks], QH + off);
            ldm_x4(ql[ks], QL + off);
        }
    }

    float o[8][4];
    #pragma unroll
    for (int dt = 0; dt < 8; dt++)
        #pragma unroll
        for (int r = 0; r < 4; r++) o[dt][r] = 0.f;
    float m0 = -1e30f, m1 = -1e30f, l0 = 0.f, l1 = 0.f;

    const int bm = lane >> 3;
    const uint32_t b_sub = (bm >> 1) * 8 + (lane & 7);
    const uint32_t b_khalf = (bm & 1) * 8;
    const uint32_t t_row = lane & 15, t_col = lane >> 4;
    const int rloc = lane >> 2;
    const int cloc = (lane & 3) * 2;

    for (int j = 0; j <= jmax; j++) {
        const uint32_t KHb = ST + (j % 3) * AT_STAGE;
        const uint32_t VHb = KHb + AT_MAT, VLb = KHb + 2*AT_MAT;

        // ---- S = Q K^T : (Qh+Ql) x Kh, 2 products ----
        float s[8][4];
        #pragma unroll
        for (int np = 0; np < 4; np++) {
            s[2*np][0]=s[2*np][1]=s[2*np][2]=s[2*np][3]=0.f;
            s[2*np+1][0]=s[2*np+1][1]=s[2*np+1][2]=s[2*np+1][3]=0.f;
            #pragma unroll
            for (int ks = 0; ks < 4; ks++) {
                uint32_t off = (np * 16 + b_sub) * AT_RW + (ks * 16 + b_khalf) * 2;
                uint32_t kh4[4];
                ldm_x4(kh4, KHb + off);
                mma16816(s[2*np],   qh[ks], &kh4[0]);
                mma16816(s[2*np],   ql[ks], &kh4[0]);
                mma16816(s[2*np+1], qh[ks], &kh4[2]);
                mma16816(s[2*np+1], ql[ks], &kh4[2]);
            }
        }

        // ---- causal mask (diagonal tiles) ----
        if (j >= 2 * qb) {
            int r0g = qb * 128 + w * 16 + rloc;
            int c0g = j * 64;
            #pragma unroll
            for (int nt = 0; nt < 8; nt++) {
                int col = c0g + nt * 8 + cloc;
                if (col     > r0g)     s[nt][0] = -1e30f;
                if (col + 1 > r0g)     s[nt][1] = -1e30f;
                if (col     > r0g + 8) s[nt][2] = -1e30f;
                if (col + 1 > r0g + 8) s[nt][3] = -1e30f;
            }
        }

        // ---- online softmax ----
        float mx0 = -1e30f, mx1 = -1e30f;
        #pragma unroll
        for (int nt = 0; nt < 8; nt++) {
            mx0 = fmaxf(mx0, fmaxf(s[nt][0], s[nt][1]));
            mx1 = fmaxf(mx1, fmaxf(s[nt][2], s[nt][3]));
        }
        mx0 = fmaxf(mx0, __shfl_xor_sync(0xffffffffu, mx0, 1));
        mx0 = fmaxf(mx0, __shfl_xor_sync(0xffffffffu, mx0, 2));
        mx1 = fmaxf(mx1, __shfl_xor_sync(0xffffffffu, mx1, 1));
        mx1 = fmaxf(mx1, __shfl_xor_sync(0xffffffffu, mx1, 2));
        float mn0 = fmaxf(m0, mx0), mn1 = fmaxf(m1, mx1);
        float cr0 = __expf(m0 - mn0), cr1 = __expf(m1 - mn1);
        float ls0 = 0.f, ls1 = 0.f;
        #pragma unroll
        for (int nt = 0; nt < 8; nt++) {
            s[nt][0] = __expf(s[nt][0] - mn0); ls0 += s[nt][0];
            s[nt][1] = __expf(s[nt][1] - mn0); ls0 += s[nt][1];
            s[nt][2] = __expf(s[nt][2] - mn1); ls1 += s[nt][2];
            s[nt][3] = __expf(s[nt][3] - mn1); ls1 += s[nt][3];
        }
        ls0 += __shfl_xor_sync(0xffffffffu, ls0, 1);
        ls0 += __shfl_xor_sync(0xffffffffu, ls0, 2);
        ls1 += __shfl_xor_sync(0xffffffffu, ls1, 1);
        ls1 += __shfl_xor_sync(0xffffffffu, ls1, 2);
        l0 = l0 * cr0 + ls0;  m0 = mn0;
        l1 = l1 * cr1 + ls1;  m1 = mn1;
        #pragma unroll
        for (int dt = 0; dt < 8; dt++) {
            o[dt][0] *= cr0; o[dt][1] *= cr0;
            o[dt][2] *= cr1; o[dt][3] *= cr1;
        }

        // ---- P fragments (fp16, unsplit) ----
        uint32_t ph[4][4];
        #pragma unroll
        for (int kt = 0; kt < 4; kt++) {
            ph[kt][0] = pack2h(s[2*kt][0],   s[2*kt][1]);
            ph[kt][1] = pack2h(s[2*kt][2],   s[2*kt][3]);
            ph[kt][2] = pack2h(s[2*kt+1][0], s[2*kt+1][1]);
            ph[kt][3] = pack2h(s[2*kt+1][2], s[2*kt+1][3]);
        }

        // ---- O += P (Vh + Vl), 2 products ----
        #pragma unroll
        for (int dp = 0; dp < 4; dp++) {
            #pragma unroll
            for (int kt = 0; kt < 4; kt++) {
                uint32_t off = (kt * 16 + t_row) * AT_RW + (dp * 2 + t_col) * 16;
                uint32_t vh4[4], vl4[4];
                ldm_x4t(vh4, VHb + off);
                ldm_x4t(vl4, VLb + off);
                mma16816(o[dp*2],   ph[kt], &vh4[0]);
                mma16816(o[dp*2],   ph[kt], &vl4[0]);
                mma16816(o[dp*2+1], ph[kt], &vh4[2]);
                mma16816(o[dp*2+1], ph[kt], &vl4[2]);
            }
        }

        // ---- pipeline ----
        __syncthreads();
        if (j + 3 <= jmax) {
            attn_load_kv(ST + (j % 3) * AT_STAGE, base, j + 3, tid);
            CP_COMMIT();
        }
        if (j + 1 <= jmax) {
            if (j + 3 <= jmax)      { CP_WAIT(2); }
            else if (j + 2 <= jmax) { CP_WAIT(1); }
            else                    { CP_WAIT(0); }
            __syncthreads();
        }
    }

    // ---- epilogue ----
    const float inv0 = 1.f / l0, inv1 = 1.f / l1;
    const int b = bh >> 4, h = bh & 15;
    const int row0 = qb * 128 + w * 16 + rloc;
    #pragma unroll
    for (int dt = 0; dt < 8; dt++) {
        int d = dt * 8 + cloc;
        size_t o0 = ((size_t)(b * TT + row0)) * EE + h * HDD + d;
        size_t o1 = o0 + (size_t)8 * EE;
        uint32_t h0, lo0, h1, lo1;
        split2(o[dt][0] * inv0, o[dt][1] * inv0, h0, lo0);
        split2(o[dt][2] * inv1, o[dt][3] * inv1, h1, lo1);
        *(uint32_t*)(g_ahi + o0) = h0; *(uint32_t*)(g_alo + o0) = lo0;
        *(uint32_t*)(g_ahi + o1) = h1; *(uint32_t*)(g_alo + o1) = lo1;
    }
}

// ---------------------------------------------------------------- launch ----
extern "C" void kernel_launch(void* const* d_in, const int* in_sizes, int n_in,
                              void* d_out, int out_size)
{
    const float* x  = (const float*)d_in[0];
    const float* Wq = (const float*)d_in[1];
    const float* Wk = (const float*)d_in[2];
    const float* Wv = (const float*)d_in[3];
    const float* Wo = (const float*)d_in[4];
    const float* bo = (const float*)d_in[5];
    float* out = (float*)d_out;

    const int smem_gemm = 2 * STAGE;
    cudaFuncSetAttribute(gemm_qkv_kernel, cudaFuncAttributeMaxDynamicSharedMemorySize, smem_gemm);
    cudaFuncSetAttribute(gemm_o_kernel,   cudaFuncAttributeMaxDynamicSharedMemorySize, smem_gemm);
    cudaFuncSetAttribute(attn_mma_kernel, cudaFuncAttributeMaxDynamicSharedMemorySize, AT_SMEM);

    conv_x_kernel<<<MM * EE / (256 * 8), 256>>>(x);
    dim3 gw(EE / 32, HDD / 32, HH * 3);
    conv_w_kernel<<<gw, 256>>>(Wq, Wk, Wv);
    conv_wo_kernel<<<EE * EE / 256, 256>>>(Wo);

    dim3 gqkv(MM / 128, EE / 128, 3);
    gemm_qkv_kernel<<<gqkv, 256, smem_gemm>>>();

    dim3 ga(TT / 128, BB * HH);
    attn_mma_kernel<<<ga, 256, AT_SMEM>>>();

    dim3 go(MM / 128, EE / 128);
    gemm_o_kernel<<<go, 256, smem_gemm>>>(bo, out);
}

// round 7
// speedup vs baseline: 4.7659x; 1.3220x over previous
#include <cuda_runtime.h>
#include <cuda_fp16.h>
#include <cstdint>
#include <math.h>

#define BB 4
#define TT 2048
#define EE 1024
#define HH 16
#define HDD 64
#define MM (BB*TT)

// ---------------------------------------------------------------- scratch ----
__device__ __half g_qhi[MM*EE], g_qlo[MM*EE];      // (b,h,t,d), pre-scaled by 1/8
__device__ __half g_khi[MM*EE];                    // fp16-only
__device__ __half g_vhi[MM*EE];                    // fp16-only
__device__ __half g_xhi[MM*EE], g_xlo[MM*EE];
__device__ __half g_ahi[MM*EE], g_alo[MM*EE];
__device__ __half g_wqhi[EE*EE];                   // transposed: [h*64+d][e], hi only
__device__ __half g_wkhi[EE*EE];
__device__ __half g_wvhi[EE*EE];
__device__ __half g_wohi[EE*EE];                   // natural: [n][k], hi only

// ---------------------------------------------------------------- helpers ----
__device__ __forceinline__ uint32_t smem_u32(const void* p) {
    uint32_t a;
    asm("{ .reg .u64 t; cvta.to.shared.u64 t, %1; cvt.u32.u64 %0, t; }" : "=r"(a) : "l"(p));
    return a;
}
__device__ __forceinline__ void cp16(uint32_t saddr, const void* g) {
    asm volatile("cp.async.cg.shared.global [%0], [%1], 16;" :: "r"(saddr), "l"(g));
}
#define CP_COMMIT() asm volatile("cp.async.commit_group;" ::: "memory")
#define CP_WAIT(n)  asm volatile("cp.async.wait_group %0;" :: "n"(n) : "memory")

__device__ __forceinline__ void ldm_x4(uint32_t* r, uint32_t addr) {
    asm volatile("ldmatrix.sync.aligned.m8n8.x4.shared.b16 {%0,%1,%2,%3}, [%4];"
                 : "=r"(r[0]), "=r"(r[1]), "=r"(r[2]), "=r"(r[3]) : "r"(addr));
}
__device__ __forceinline__ void ldm_x4t(uint32_t* r, uint32_t addr) {
    asm volatile("ldmatrix.sync.aligned.m8n8.x4.trans.shared.b16 {%0,%1,%2,%3}, [%4];"
                 : "=r"(r[0]), "=r"(r[1]), "=r"(r[2]), "=r"(r[3]) : "r"(addr));
}
__device__ __forceinline__ void mma16816(float* c, const uint32_t* a, const uint32_t* b) {
    asm volatile("mma.sync.aligned.m16n8k16.row.col.f32.f16.f16.f32 "
                 "{%0,%1,%2,%3}, {%4,%5,%6,%7}, {%8,%9}, {%0,%1,%2,%3};"
                 : "+f"(c[0]), "+f"(c[1]), "+f"(c[2]), "+f"(c[3])
                 : "r"(a[0]), "r"(a[1]), "r"(a[2]), "r"(a[3]), "r"(b[0]), "r"(b[1]));
}

__device__ __forceinline__ void split1(float v, ushort& h, ushort& l) {
    __half hb = __float2half_rn(v);
    float rem = v - __half2float(hb);
    __half lb = __float2half_rn(rem);
    h = __half_as_ushort(hb); l = __half_as_ushort(lb);
}
__device__ __forceinline__ void split2(float a, float b, uint32_t& hi, uint32_t& lo) {
    ushort h0, l0, h1, l1;
    split1(a, h0, l0); split1(b, h1, l1);
    hi = (uint32_t)h0 | ((uint32_t)h1 << 16);
    lo = (uint32_t)l0 | ((uint32_t)l1 << 16);
}
__device__ __forceinline__ uint32_t pack2h(float a, float b) {
    __half2 h = __floats2half2_rn(a, b);
    return *(uint32_t*)&h;
}

// ---------------------------------------------------------------- converts --
__global__ __launch_bounds__(256) void conv_x_kernel(const float* __restrict__ x) {
    size_t i = ((size_t)blockIdx.x * 256 + threadIdx.x) * 8;
    float4 a = *(const float4*)(x + i);
    float4 b = *(const float4*)(x + i + 4);
    float v[8] = {a.x,a.y,a.z,a.w,b.x,b.y,b.z,b.w};
    ushort hs[8], ls[8];
    #pragma unroll
    for (int j = 0; j < 8; j++) split1(v[j], hs[j], ls[j]);
    uint4 ph = make_uint4(hs[0]|(hs[1]<<16), hs[2]|(hs[3]<<16), hs[4]|(hs[5]<<16), hs[6]|(hs[7]<<16));
    uint4 pl = make_uint4(ls[0]|(ls[1]<<16), ls[2]|(ls[3]<<16), ls[4]|(ls[5]<<16), ls[6]|(ls[7]<<16));
    *(uint4*)(g_xhi + i) = ph;
    *(uint4*)(g_xlo + i) = pl;
}

// W[h][e][d] -> WT[h*64+d][e] (hi only); blockIdx.z = wsel*16 + h
__global__ __launch_bounds__(256) void conv_w_kernel(const float* __restrict__ Wq,
        const float* __restrict__ Wk, const float* __restrict__ Wv) {
    __shared__ float ts[32][33];
    const int wsel = blockIdx.z >> 4;
    const int h  = blockIdx.z & 15;
    const int d0 = blockIdx.y * 32;
    const int e0 = blockIdx.x * 32;
    const float* W = (wsel == 0) ? Wq : (wsel == 1) ? Wk : Wv;
    __half* hi = (wsel == 0) ? g_wqhi : (wsel == 1) ? g_wkhi : g_wvhi;
    const int tx = threadIdx.x & 31, ty = threadIdx.x >> 5;
    #pragma unroll
    for (int r = 0; r < 4; r++)
        ts[ty + r*8][tx] = W[((size_t)h * EE + e0 + ty + r*8) * HDD + d0 + tx];
    __syncthreads();
    #pragma unroll
    for (int r = 0; r < 4; r++) {
        size_t o = (size_t)(h * 64 + d0 + ty + r*8) * EE + e0 + tx;
        hi[o] = __float2half_rn(ts[tx][ty + r*8]);
    }
}

__global__ __launch_bounds__(256) void conv_wo_kernel(const float* __restrict__ W) {
    int idx = blockIdx.x * 256 + threadIdx.x;
    g_wohi[idx] = __float2half_rn(W[idx]);
}

// ------------------------------------------ HMMA 2-product fp16 GEMM core ----
// C = A_exact(hi+lo) @ B_hi^T. CTA 128x128, BK=32, 3-stage cp.async ring.
#define ROWB   80
#define MATB   (128*ROWB)
#define OFF_AH 0
#define OFF_AL (1*MATB)
#define OFF_BH (2*MATB)
#define STAGE3 (3*MATB)                 // 30720 B; x3 stages = 92160

__device__ __forceinline__ void stage_load(uint32_t base,
    const __half* __restrict__ Ahi, const __half* __restrict__ Alo,
    const __half* __restrict__ Bhi, int m0, int n0, int k0, int tid)
{
    #pragma unroll
    for (int p = 0; p < 2; p++) {
        int chunk = p * 256 + tid;
        int row = chunk >> 2, ch = chunk & 3;
        uint32_t so = row * ROWB + ch * 16;
        size_t ga = (size_t)(m0 + row) * EE + k0 + ch * 8;
        size_t gb = (size_t)(n0 + row) * EE + k0 + ch * 8;
        cp16(base + OFF_AH + so, Ahi + ga);
        cp16(base + OFF_AL + so, Alo + ga);
        cp16(base + OFF_BH + so, Bhi + gb);
    }
}

__device__ __forceinline__ void gemm_core(
    const __half* __restrict__ Ahi, const __half* __restrict__ Alo,
    const __half* __restrict__ Bhi,
    int m0, int n0, float acc[4][4][4], char* smem)
{
    const int tid = threadIdx.x;
    const int lane = tid & 31, wid = tid >> 5;
    const int wm = wid >> 2, wn = wid & 3;
    const uint32_t sb = smem_u32(smem);

    const uint32_t a_row = lane & 15, a_half = lane >> 4;
    const int bm = lane >> 3;
    const uint32_t b_sub = (bm >> 1) * 8 + (lane & 7);
    const uint32_t b_khalf = (bm & 1) * 8;

    const int NKT = EE / 32;            // 32
    stage_load(sb,          Ahi, Alo, Bhi, m0, n0, 0,  tid); CP_COMMIT();
    stage_load(sb + STAGE3, Ahi, Alo, Bhi, m0, n0, 32, tid); CP_COMMIT();
    CP_WAIT(1);
    __syncthreads();

    for (int kt = 0; kt < NKT; kt++) {
        // prefetch kt+2 into buffer (kt+2)%3 (free since end-of-(kt-1) sync)
        if (kt + 2 < NKT) {
            stage_load(sb + ((kt + 2) % 3) * STAGE3, Ahi, Alo, Bhi,
                       m0, n0, (kt + 2) * 32, tid);
            CP_COMMIT();
        }

        const uint32_t st = sb + (kt % 3) * STAGE3;
        #pragma unroll
        for (int ks = 0; ks < 2; ks++) {
            uint32_t ah[4][4], al[4][4], bh[2][4];
            const uint32_t kb  = (ks * 16 + a_half * 8) * 2;
            const uint32_t kbB = (ks * 16 + b_khalf) * 2;
            #pragma unroll
            for (int mi = 0; mi < 4; mi++)
                ldm_x4(ah[mi], st + OFF_AH + (wm * 64 + mi * 16 + a_row) * ROWB + kb);
            #pragma unroll
            for (int np = 0; np < 2; np++)
                ldm_x4(bh[np], st + OFF_BH + (wn * 32 + np * 16 + b_sub) * ROWB + kbB);
            #pragma unroll
            for (int mi = 0; mi < 4; mi++)
                #pragma unroll
                for (int np = 0; np < 2; np++) {
                    mma16816(acc[mi][np*2],   ah[mi], &bh[np][0]);
                    mma16816(acc[mi][np*2+1], ah[mi], &bh[np][2]);
                }
            #pragma unroll
            for (int mi = 0; mi < 4; mi++)
                ldm_x4(al[mi], st + OFF_AL + (wm * 64 + mi * 16 + a_row) * ROWB + kb);
            #pragma unroll
            for (int mi = 0; mi < 4; mi++)
                #pragma unroll
                for (int np = 0; np < 2; np++) {
                    mma16816(acc[mi][np*2],   al[mi], &bh[np][0]);
                    mma16816(acc[mi][np*2+1], al[mi], &bh[np][2]);
                }
        }

        if (kt + 1 < NKT) {
            if (kt + 2 < NKT) { CP_WAIT(1); } else { CP_WAIT(0); }
            __syncthreads();
        }
    }
}

// QKV projections in one launch: blockIdx.z selects q/k/v.
__global__ __launch_bounds__(256)
void gemm_qkv_kernel()
{
    extern __shared__ char smem[];
    const int z = blockIdx.z;
    const int m0 = blockIdx.x * 128;
    const int n0 = blockIdx.y * 128;

    const __half* Bh = (z == 0) ? g_wqhi : (z == 1) ? g_wkhi : g_wvhi;

    float acc[4][4][4];
    #pragma unroll
    for (int i = 0; i < 4; i++)
        #pragma unroll
        for (int j = 0; j < 4; j++)
            #pragma unroll
            for (int r = 0; r < 4; r++) acc[i][j][r] = 0.f;

    gemm_core(g_xhi, g_xlo, Bh, m0, n0, acc, smem);

    __half* Chi = (z == 0) ? g_qhi : (z == 1) ? g_khi : g_vhi;
    __half* Clo = g_qlo;                          // only used for z==0
    const float scale = (z == 0) ? 0.125f : 1.0f;
    const bool wlo = (z == 0);

    const int lane = threadIdx.x & 31, wid = threadIdx.x >> 5;
    const int wm = wid >> 2, wn = wid & 3;
    const int rbase = lane >> 2;
    const int cbase = (lane & 3) * 2;
    #pragma unroll
    for (int mi = 0; mi < 4; mi++) {
        #pragma unroll
        for (int ni = 0; ni < 4; ni++) {
            int mrow = m0 + wm * 64 + mi * 16 + rbase;
            int ncol = n0 + wn * 32 + ni * 8 + cbase;
            int head = ncol >> 6, d = ncol & 63;
            int b = mrow >> 11, t = mrow & 2047;
            size_t o0 = ((size_t)(b * HH + head) * TT + t) * HDD + d;
            size_t o1 = o0 + 8 * HDD;
            uint32_t h0, l0, h1, l1;
            split2(acc[mi][ni][0] * scale, acc[mi][ni][1] * scale, h0, l0);
            split2(acc[mi][ni][2] * scale, acc[mi][ni][3] * scale, h1, l1);
            *(uint32_t*)(Chi + o0) = h0;
            *(uint32_t*)(Chi + o1) = h1;
            if (wlo) {
                *(uint32_t*)(Clo + o0) = l0;
                *(uint32_t*)(Clo + o1) = l1;
            }
        }
    }
}

// Output projection: out = att @ Wo^T + bo (fp32 out)
__global__ __launch_bounds__(256)
void gemm_o_kernel(const float* __restrict__ bias, float* __restrict__ C)
{
    extern __shared__ char smem[];
    const int m0 = blockIdx.x * 128;
    const int n0 = blockIdx.y * 128;

    float acc[4][4][4];
    #pragma unroll
    for (int i = 0; i < 4; i++)
        #pragma unroll
        for (int j = 0; j < 4; j++)
            #pragma unroll
            for (int r = 0; r < 4; r++) acc[i][j][r] = 0.f;

    gemm_core(g_ahi, g_alo, g_wohi, m0, n0, acc, smem);

    const int lane = threadIdx.x & 31, wid = threadIdx.x >> 5;
    const int wm = wid >> 2, wn = wid & 3;
    const int rbase = lane >> 2;
    const int cbase = (lane & 3) * 2;
    #pragma unroll
    for (int mi = 0; mi < 4; mi++) {
        #pragma unroll
        for (int ni = 0; ni < 4; ni++) {
            int mrow = m0 + wm * 64 + mi * 16 + rbase;
            int ncol = n0 + wn * 32 + ni * 8 + cbase;
            float2 bv = *(const float2*)(bias + ncol);
            float* dst = C + (size_t)mrow * EE + ncol;
            *(float2*)dst = make_float2(acc[mi][ni][0] + bv.x, acc[mi][ni][1] + bv.y);
            *(float2*)(dst + 8 * EE) = make_float2(acc[mi][ni][2] + bv.x,
                                                   acc[mi][ni][3] + bv.y);
        }
    }
}

// ---------------- HMMA flash attention: 2-product S, 1-product PV ------------
// CTA: 128 q-rows. Stage: {Kh, Vh}. 3-stage cp.async ring.
#define AT_RW    144
#define AT_MAT   (64*AT_RW)            // 9216
#define AT_QMAT  (128*AT_RW)           // 18432
#define AT_ST    (2*AT_QMAT)           // 36864 (QH+QL)
#define AT_STAGE (2*AT_MAT)            // 18432
#define AT_SMEM  (AT_ST + 3*AT_STAGE)  // 92160

__device__ __forceinline__ void attn_load_kv(uint32_t dst, size_t base, int j, int tid)
{
    const __half* mats[2] = {g_khi, g_vhi};
    #pragma unroll
    for (int p = 0; p < 4; p++) {
        int idx = p * 256 + tid;          // 0..1023
        int mat = idx >> 9, rem = idx & 511;
        int row = rem >> 3, ch = rem & 7;
        cp16(dst + mat * AT_MAT + row * AT_RW + ch * 16,
             mats[mat] + base + (size_t)(j * 64 + row) * HDD + ch * 8);
    }
}

__global__ __launch_bounds__(256)
void attn_mma_kernel()
{
    extern __shared__ char smem[];
    const int tid = threadIdx.x, lane = tid & 31, w = tid >> 5;
    const int qb = (gridDim.x - 1) - blockIdx.x;
    const int bh = blockIdx.y;
    const int jmax = 2 * qb + 1;                   // >= 1 always
    const size_t base = (size_t)bh * TT * HDD;
    const uint32_t sb = smem_u32(smem);
    const uint32_t QH = sb, QL = QH + AT_QMAT;
    const uint32_t ST = sb + AT_ST;

    // prologue: Q + kv0 (group), kv1 (group)
    {
        const __half* qm[2] = {g_qhi, g_qlo};
        #pragma unroll
        for (int p = 0; p < 8; p++) {
            int idx = p * 256 + tid;
            int mat = idx >> 10, rem = idx & 1023;
            int row = rem >> 3, ch = rem & 7;
            cp16(QH + mat * AT_QMAT + row * AT_RW + ch * 16,
                 qm[mat] + base + (size_t)(qb * 128 + row) * HDD + ch * 8);
        }
        attn_load_kv(ST, base, 0, tid);
        CP_COMMIT();
    }
    attn_load_kv(ST + AT_STAGE, base, 1, tid);
    CP_COMMIT();
    CP_WAIT(1);
    __syncthreads();

    uint32_t qh[4][4], ql[4][4];
    {
        const uint32_t a_row = lane & 15, a_half = lane >> 4;
        #pragma unroll
        for (int ks = 0; ks < 4; ks++) {
            uint32_t off = (w * 16 + a_row) * AT_RW + (ks * 16 + a_half * 8) * 2;
            ldm_x4(qh[ks], QH + off);
            ldm_x4(ql[ks], QL + off);
        }
    }

    float o[8][4];
    #pragma unroll
    for (int dt = 0; dt < 8; dt++)
        #pragma unroll
        for (int r = 0; r < 4; r++) o[dt][r] = 0.f;
    float m0 = -1e30f, m1 = -1e30f, l0 = 0.f, l1 = 0.f;

    const int bm = lane >> 3;
    const uint32_t b_sub = (bm >> 1) * 8 + (lane & 7);
    const uint32_t b_khalf = (bm & 1) * 8;
    const uint32_t t_row = lane & 15, t_col = lane >> 4;
    const int rloc = lane >> 2;
    const int cloc = (lane & 3) * 2;

    for (int j = 0; j <= jmax; j++) {
        // prefetch j+2 into buffer (j+2)%3 (freed by end-of-(j-1) sync)
        if (j + 2 <= jmax) {
            attn_load_kv(ST + ((j + 2) % 3) * AT_STAGE, base, j + 2, tid);
            CP_COMMIT();
        }

        const uint32_t KHb = ST + (j % 3) * AT_STAGE;
        const uint32_t VHb = KHb + AT_MAT;

        // ---- S = Q K^T : (Qh+Ql) x Kh ----
        float s[8][4];
        #pragma unroll
        for (int np = 0; np < 4; np++) {
            s[2*np][0]=s[2*np][1]=s[2*np][2]=s[2*np][3]=0.f;
            s[2*np+1][0]=s[2*np+1][1]=s[2*np+1][2]=s[2*np+1][3]=0.f;
            #pragma unroll
            for (int ks = 0; ks < 4; ks++) {
                uint32_t off = (np * 16 + b_sub) * AT_RW + (ks * 16 + b_khalf) * 2;
                uint32_t kh4[4];
                ldm_x4(kh4, KHb + off);
                mma16816(s[2*np],   qh[ks], &kh4[0]);
                mma16816(s[2*np],   ql[ks], &kh4[0]);
                mma16816(s[2*np+1], qh[ks], &kh4[2]);
                mma16816(s[2*np+1], ql[ks], &kh4[2]);
            }
        }

        // ---- causal mask (diagonal tiles) ----
        if (j >= 2 * qb) {
            int r0g = qb * 128 + w * 16 + rloc;
            int c0g = j * 64;
            #pragma unroll
            for (int nt = 0; nt < 8; nt++) {
                int col = c0g + nt * 8 + cloc;
                if (col     > r0g)     s[nt][0] = -1e30f;
                if (col + 1 > r0g)     s[nt][1] = -1e30f;
                if (col     > r0g + 8) s[nt][2] = -1e30f;
                if (col + 1 > r0g + 8) s[nt][3] = -1e30f;
            }
        }

        // ---- online softmax ----
        float mx0 = -1e30f, mx1 = -1e30f;
        #pragma unroll
        for (int nt = 0; nt < 8; nt++) {
            mx0 = fmaxf(mx0, fmaxf(s[nt][0], s[nt][1]));
            mx1 = fmaxf(mx1, fmaxf(s[nt][2], s[nt][3]));
        }
        mx0 = fmaxf(mx0, __shfl_xor_sync(0xffffffffu, mx0, 1));
        mx0 = fmaxf(mx0, __shfl_xor_sync(0xffffffffu, mx0, 2));
        mx1 = fmaxf(mx1, __shfl_xor_sync(0xffffffffu, mx1, 1));
        mx1 = fmaxf(mx1, __shfl_xor_sync(0xffffffffu, mx1, 2));
        float mn0 = fmaxf(m0, mx0), mn1 = fmaxf(m1, mx1);
        float cr0 = __expf(m0 - mn0), cr1 = __expf(m1 - mn1);
        float ls0 = 0.f, ls1 = 0.f;
        #pragma unroll
        for (int nt = 0; nt < 8; nt++) {
            s[nt][0] = __expf(s[nt][0] - mn0); ls0 += s[nt][0];
            s[nt][1] = __expf(s[nt][1] - mn0); ls0 += s[nt][1];
            s[nt][2] = __expf(s[nt][2] - mn1); ls1 += s[nt][2];
            s[nt][3] = __expf(s[nt][3] - mn1); ls1 += s[nt][3];
        }
        ls0 += __shfl_xor_sync(0xffffffffu, ls0, 1);
        ls0 += __shfl_xor_sync(0xffffffffu, ls0, 2);
        ls1 += __shfl_xor_sync(0xffffffffu, ls1, 1);
        ls1 += __shfl_xor_sync(0xffffffffu, ls1, 2);
        l0 = l0 * cr0 + ls0;  m0 = mn0;
        l1 = l1 * cr1 + ls1;  m1 = mn1;
        #pragma unroll
        for (int dt = 0; dt < 8; dt++) {
            o[dt][0] *= cr0; o[dt][1] *= cr0;
            o[dt][2] *= cr1; o[dt][3] *= cr1;
        }

        // ---- P fragments (fp16) ----
        uint32_t ph[4][4];
        #pragma unroll
        for (int kt = 0; kt < 4; kt++) {
            ph[kt][0] = pack2h(s[2*kt][0],   s[2*kt][1]);
            ph[kt][1] = pack2h(s[2*kt][2],   s[2*kt][3]);
            ph[kt][2] = pack2h(s[2*kt+1][0], s[2*kt+1][1]);
            ph[kt][3] = pack2h(s[2*kt+1][2], s[2*kt+1][3]);
        }

        // ---- O += P Vh (1 product) ----
        #pragma unroll
        for (int dp = 0; dp < 4; dp++) {
            #pragma unroll
            for (int kt = 0; kt < 4; kt++) {
                uint32_t off = (kt * 16 + t_row) * AT_RW + (dp * 2 + t_col) * 16;
                uint32_t vh4[4];
                ldm_x4t(vh4, VHb + off);
                mma16816(o[dp*2],   ph[kt], &vh4[0]);
                mma16816(o[dp*2+1], ph[kt], &vh4[2]);
            }
        }

        if (j < jmax) {
            if (j + 2 <= jmax) { CP_WAIT(1); } else { CP_WAIT(0); }
            __syncthreads();
        }
    }

    // ---- epilogue ----
    const float inv0 = 1.f / l0, inv1 = 1.f / l1;
    const int b = bh >> 4, h = bh & 15;
    const int row0 = qb * 128 + w * 16 + rloc;
    #pragma unroll
    for (int dt = 0; dt < 8; dt++) {
        int d = dt * 8 + cloc;
        size_t o0 = ((size_t)(b * TT + row0)) * EE + h * HDD + d;
        size_t o1 = o0 + (size_t)8 * EE;
        uint32_t h0, lo0, h1, lo1;
        split2(o[dt][0] * inv0, o[dt][1] * inv0, h0, lo0);
        split2(o[dt][2] * inv1, o[dt][3] * inv1, h1, lo1);
        *(uint32_t*)(g_ahi + o0) = h0; *(uint32_t*)(g_alo + o0) = lo0;
        *(uint32_t*)(g_ahi + o1) = h1; *(uint32_t*)(g_alo + o1) = lo1;
    }
}

// ---------------------------------------------------------------- launch ----
extern "C" void kernel_launch(void* const* d_in, const int* in_sizes, int n_in,
                              void* d_out, int out_size)
{
    const float* x  = (const float*)d_in[0];
    const float* Wq = (const float*)d_in[1];
    const float* Wk = (const float*)d_in[2];
    const float* Wv = (const float*)d_in[3];
    const float* Wo = (const float*)d_in[4];
    const float* bo = (const float*)d_in[5];
    float* out = (float*)d_out;

    const int smem_gemm = 3 * STAGE3;   // 92160
    cudaFuncSetAttribute(gemm_qkv_kernel, cudaFuncAttributeMaxDynamicSharedMemorySize, smem_gemm);
    cudaFuncSetAttribute(gemm_o_kernel,   cudaFuncAttributeMaxDynamicSharedMemorySize, smem_gemm);
    cudaFuncSetAttribute(attn_mma_kernel, cudaFuncAttributeMaxDynamicSharedMemorySize, AT_SMEM);

    conv_x_kernel<<<MM * EE / (256 * 8), 256>>>(x);
    dim3 gw(EE / 32, HDD / 32, HH * 3);
    conv_w_kernel<<<gw, 256>>>(Wq, Wk, Wv);
    conv_wo_kernel<<<EE * EE / 256, 256>>>(Wo);

    dim3 gqkv(MM / 128, EE / 128, 3);
    gemm_qkv_kernel<<<gqkv, 256, smem_gemm>>>();

    dim3 ga(TT / 128, BB * HH);
    attn_mma_kernel<<<ga, 256, AT_SMEM>>>();

    dim3 go(MM / 128, EE / 128);
    gemm_o_kernel<<<go, 256, smem_gemm>>>(bo, out);
}

// round 8
// speedup vs baseline: 7.4002x; 1.5527x over previous
#include <cuda_runtime.h>
#include <cuda_fp16.h>
#include <cstdint>
#include <math.h>

#define BB 4
#define TT 2048
#define EE 1024
#define HH 16
#define HDD 64
#define MM (BB*TT)

// ---------------------------------------------------------------- scratch ----
__device__ __half g_q[MM*EE];        // (b,h,t,d), pre-scaled by 1/8
__device__ __half g_k[MM*EE];
__device__ __half g_v[MM*EE];
__device__ __half g_x[MM*EE];
__device__ __half g_a[MM*EE];        // attention out (concat heads)
__device__ __half g_wq[EE*EE];       // transposed: [h*64+d][e]
__device__ __half g_wk[EE*EE];
__device__ __half g_wv[EE*EE];
__device__ __half g_wo[EE*EE];       // natural: [n][k]

// ---------------------------------------------------------------- helpers ----
__device__ __forceinline__ uint32_t smem_u32(const void* p) {
    uint32_t a;
    asm("{ .reg .u64 t; cvta.to.shared.u64 t, %1; cvt.u32.u64 %0, t; }" : "=r"(a) : "l"(p));
    return a;
}
__device__ __forceinline__ void cp16(uint32_t saddr, const void* g) {
    asm volatile("cp.async.cg.shared.global [%0], [%1], 16;" :: "r"(saddr), "l"(g));
}
#define CP_COMMIT() asm volatile("cp.async.commit_group;" ::: "memory")
#define CP_WAIT(n)  asm volatile("cp.async.wait_group %0;" :: "n"(n) : "memory")

__device__ __forceinline__ void ldm_x4(uint32_t* r, uint32_t addr) {
    asm volatile("ldmatrix.sync.aligned.m8n8.x4.shared.b16 {%0,%1,%2,%3}, [%4];"
                 : "=r"(r[0]), "=r"(r[1]), "=r"(r[2]), "=r"(r[3]) : "r"(addr));
}
__device__ __forceinline__ void ldm_x4t(uint32_t* r, uint32_t addr) {
    asm volatile("ldmatrix.sync.aligned.m8n8.x4.trans.shared.b16 {%0,%1,%2,%3}, [%4];"
                 : "=r"(r[0]), "=r"(r[1]), "=r"(r[2]), "=r"(r[3]) : "r"(addr));
}
__device__ __forceinline__ void mma16816(float* c, const uint32_t* a, const uint32_t* b) {
    asm volatile("mma.sync.aligned.m16n8k16.row.col.f32.f16.f16.f32 "
                 "{%0,%1,%2,%3}, {%4,%5,%6,%7}, {%8,%9}, {%0,%1,%2,%3};"
                 : "+f"(c[0]), "+f"(c[1]), "+f"(c[2]), "+f"(c[3])
                 : "r"(a[0]), "r"(a[1]), "r"(a[2]), "r"(a[3]), "r"(b[0]), "r"(b[1]));
}
__device__ __forceinline__ uint32_t pack2h(float a, float b) {
    __half2 h = __floats2half2_rn(a, b);
    return *(uint32_t*)&h;
}

// ---------------------------------------------------------------- converts --
__global__ __launch_bounds__(256) void conv_x_kernel(const float* __restrict__ x) {
    size_t i = ((size_t)blockIdx.x * 256 + threadIdx.x) * 8;
    float4 a = *(const float4*)(x + i);
    float4 b = *(const float4*)(x + i + 4);
    uint4 ph = make_uint4(pack2h(a.x, a.y), pack2h(a.z, a.w),
                          pack2h(b.x, b.y), pack2h(b.z, b.w));
    *(uint4*)(g_x + i) = ph;
}

// W[h][e][d] -> WT[h*64+d][e]; blockIdx.z = wsel*16 + h
__global__ __launch_bounds__(256) void conv_w_kernel(const float* __restrict__ Wq,
        const float* __restrict__ Wk, const float* __restrict__ Wv) {
    __shared__ float ts[32][33];
    const int wsel = blockIdx.z >> 4;
    const int h  = blockIdx.z & 15;
    const int d0 = blockIdx.y * 32;
    const int e0 = blockIdx.x * 32;
    const float* W = (wsel == 0) ? Wq : (wsel == 1) ? Wk : Wv;
    __half* dst = (wsel == 0) ? g_wq : (wsel == 1) ? g_wk : g_wv;
    const int tx = threadIdx.x & 31, ty = threadIdx.x >> 5;
    #pragma unroll
    for (int r = 0; r < 4; r++)
        ts[ty + r*8][tx] = W[((size_t)h * EE + e0 + ty + r*8) * HDD + d0 + tx];
    __syncthreads();
    #pragma unroll
    for (int r = 0; r < 4; r++) {
        size_t o = (size_t)(h * 64 + d0 + ty + r*8) * EE + e0 + tx;
        dst[o] = __float2half_rn(ts[tx][ty + r*8]);
    }
}

__global__ __launch_bounds__(256) void conv_wo_kernel(const float* __restrict__ W) {
    int idx = blockIdx.x * 256 + threadIdx.x;
    g_wo[idx] = __float2half_rn(W[idx]);
}

// ------------------------------------------ HMMA fp16 GEMM core (1 product) --
// C = A @ B^T (B stored [n][k]). CTA 128x128, BK=32, 4-stage cp.async ring.
#define ROWB   80
#define MATB   (128*ROWB)
#define OFF_B  MATB
#define STAGE2 (2*MATB)                 // 20480 B; x4 stages = 81920

__device__ __forceinline__ void stage_load(uint32_t base,
    const __half* __restrict__ A, const __half* __restrict__ B,
    int m0, int n0, int k0, int tid)
{
    #pragma unroll
    for (int p = 0; p < 2; p++) {
        int chunk = p * 256 + tid;
        int row = chunk >> 2, ch = chunk & 3;
        uint32_t so = row * ROWB + ch * 16;
        cp16(base + so,         A + (size_t)(m0 + row) * EE + k0 + ch * 8);
        cp16(base + OFF_B + so, B + (size_t)(n0 + row) * EE + k0 + ch * 8);
    }
}

__device__ __forceinline__ void gemm_core(
    const __half* __restrict__ A, const __half* __restrict__ B,
    int m0, int n0, float acc[4][4][4], char* smem)
{
    const int tid = threadIdx.x;
    const int lane = tid & 31, wid = tid >> 5;
    const int wm = wid >> 2, wn = wid & 3;
    const uint32_t sb = smem_u32(smem);

    const uint32_t a_row = lane & 15, a_half = lane >> 4;
    const int bm = lane >> 3;
    const uint32_t b_sub = (bm >> 1) * 8 + (lane & 7);
    const uint32_t b_khalf = (bm & 1) * 8;

    const int NKT = EE / 32;            // 32
    stage_load(sb,              A, B, m0, n0, 0,  tid); CP_COMMIT();
    stage_load(sb + STAGE2,     A, B, m0, n0, 32, tid); CP_COMMIT();
    stage_load(sb + 2 * STAGE2, A, B, m0, n0, 64, tid); CP_COMMIT();
    CP_WAIT(2);
    __syncthreads();

    for (int kt = 0; kt < NKT; kt++) {
        // prefetch kt+3 into buffer (kt+3)%4 == (kt-1)%4 (freed by end-of-(kt-1) sync)
        if (kt + 3 < NKT) {
            stage_load(sb + ((kt + 3) & 3) * STAGE2, A, B, m0, n0, (kt + 3) * 32, tid);
            CP_COMMIT();
        }

        const uint32_t st = sb + (kt & 3) * STAGE2;
        #pragma unroll
        for (int ks = 0; ks < 2; ks++) {
            uint32_t ah[4][4], bh[2][4];
            const uint32_t kb  = (ks * 16 + a_half * 8) * 2;
            const uint32_t kbB = (ks * 16 + b_khalf) * 2;
            #pragma unroll
            for (int mi = 0; mi < 4; mi++)
                ldm_x4(ah[mi], st + (wm * 64 + mi * 16 + a_row) * ROWB + kb);
            #pragma unroll
            for (int np = 0; np < 2; np++)
                ldm_x4(bh[np], st + OFF_B + (wn * 32 + np * 16 + b_sub) * ROWB + kbB);
            #pragma unroll
            for (int mi = 0; mi < 4; mi++)
                #pragma unroll
                for (int np = 0; np < 2; np++) {
                    mma16816(acc[mi][np*2],   ah[mi], &bh[np][0]);
                    mma16816(acc[mi][np*2+1], ah[mi], &bh[np][2]);
                }
        }

        if (kt + 1 < NKT) {
            if (kt + 3 < NKT)      { CP_WAIT(2); }
            else if (kt + 2 < NKT) { CP_WAIT(1); }
            else                   { CP_WAIT(0); }
            __syncthreads();
        }
    }
}

// QKV projections in one launch: blockIdx.z selects q/k/v.
__global__ __launch_bounds__(256)
void gemm_qkv_kernel()
{
    extern __shared__ char smem[];
    const int z = blockIdx.z;
    const int m0 = blockIdx.x * 128;
    const int n0 = blockIdx.y * 128;

    const __half* Bh = (z == 0) ? g_wq : (z == 1) ? g_wk : g_wv;

    float acc[4][4][4];
    #pragma unroll
    for (int i = 0; i < 4; i++)
        #pragma unroll
        for (int j = 0; j < 4; j++)
            #pragma unroll
            for (int r = 0; r < 4; r++) acc[i][j][r] = 0.f;

    gemm_core(g_x, Bh, m0, n0, acc, smem);

    __half* C = (z == 0) ? g_q : (z == 1) ? g_k : g_v;
    const float scale = (z == 0) ? 0.125f : 1.0f;

    const int lane = threadIdx.x & 31, wid = threadIdx.x >> 5;
    const int wm = wid >> 2, wn = wid & 3;
    const int rbase = lane >> 2;
    const int cbase = (lane & 3) * 2;
    #pragma unroll
    for (int mi = 0; mi < 4; mi++) {
        #pragma unroll
        for (int ni = 0; ni < 4; ni++) {
            int mrow = m0 + wm * 64 + mi * 16 + rbase;
            int ncol = n0 + wn * 32 + ni * 8 + cbase;
            int head = ncol >> 6, d = ncol & 63;
            int b = mrow >> 11, t = mrow & 2047;
            size_t o0 = ((size_t)(b * HH + head) * TT + t) * HDD + d;
            size_t o1 = o0 + 8 * HDD;
            *(uint32_t*)(C + o0) = pack2h(acc[mi][ni][0] * scale, acc[mi][ni][1] * scale);
            *(uint32_t*)(C + o1) = pack2h(acc[mi][ni][2] * scale, acc[mi][ni][3] * scale);
        }
    }
}

// Output projection: out = att @ Wo^T + bo (fp32 out)
__global__ __launch_bounds__(256)
void gemm_o_kernel(const float* __restrict__ bias, float* __restrict__ C)
{
    extern __shared__ char smem[];
    const int m0 = blockIdx.x * 128;
    const int n0 = blockIdx.y * 128;

    float acc[4][4][4];
    #pragma unroll
    for (int i = 0; i < 4; i++)
        #pragma unroll
        for (int j = 0; j < 4; j++)
            #pragma unroll
            for (int r = 0; r < 4; r++) acc[i][j][r] = 0.f;

    gemm_core(g_a, g_wo, m0, n0, acc, smem);

    const int lane = threadIdx.x & 31, wid = threadIdx.x >> 5;
    const int wm = wid >> 2, wn = wid & 3;
    const int rbase = lane >> 2;
    const int cbase = (lane & 3) * 2;
    #pragma unroll
    for (int mi = 0; mi < 4; mi++) {
        #pragma unroll
        for (int ni = 0; ni < 4; ni++) {
            int mrow = m0 + wm * 64 + mi * 16 + rbase;
            int ncol = n0 + wn * 32 + ni * 8 + cbase;
            float2 bv = *(const float2*)(bias + ncol);
            float* dst = C + (size_t)mrow * EE + ncol;
            *(float2*)dst = make_float2(acc[mi][ni][0] + bv.x, acc[mi][ni][1] + bv.y);
            *(float2*)(dst + 8 * EE) = make_float2(acc[mi][ni][2] + bv.x,
                                                   acc[mi][ni][3] + bv.y);
        }
    }
}

// ---------------- HMMA flash attention: pure fp16, 1-product S and PV --------
// CTA: 128 q-rows. Stage: {K, V}. 3-stage cp.async ring.
#define AT_RW    144
#define AT_MAT   (64*AT_RW)            // 9216
#define AT_QMAT  (128*AT_RW)           // 18432
#define AT_ST    AT_QMAT               // Q only
#define AT_STAGE (2*AT_MAT)            // 18432
#define AT_SMEM  (AT_ST + 3*AT_STAGE)  // 73728

__device__ __forceinline__ void attn_load_kv(uint32_t dst, size_t base, int j, int tid)
{
    const __half* mats[2] = {g_k, g_v};
    #pragma unroll
    for (int p = 0; p < 4; p++) {
        int idx = p * 256 + tid;          // 0..1023
        int mat = idx >> 9, rem = idx & 511;
        int row = rem >> 3, ch = rem & 7;
        cp16(dst + mat * AT_MAT + row * AT_RW + ch * 16,
             mats[mat] + base + (size_t)(j * 64 + row) * HDD + ch * 8);
    }
}

__global__ __launch_bounds__(256)
void attn_mma_kernel()
{
    extern __shared__ char smem[];
    const int tid = threadIdx.x, lane = tid & 31, w = tid >> 5;
    const int qb = (gridDim.x - 1) - blockIdx.x;
    const int bh = blockIdx.y;
    const int jmax = 2 * qb + 1;
    const size_t base = (size_t)bh * TT * HDD;
    const uint32_t sb = smem_u32(smem);
    const uint32_t QH = sb;
    const uint32_t ST = sb + AT_ST;

    // prologue: Q + kv0, kv1
    {
        #pragma unroll
        for (int p = 0; p < 4; p++) {
            int idx = p * 256 + tid;      // 0..1023
            int row = idx >> 3, ch = idx & 7;
            cp16(QH + row * AT_RW + ch * 16,
                 g_q + base + (size_t)(qb * 128 + row) * HDD + ch * 8);
        }
        attn_load_kv(ST, base, 0, tid);
        CP_COMMIT();
    }
    attn_load_kv(ST + AT_STAGE, base, 1, tid);
    CP_COMMIT();
    CP_WAIT(1);
    __syncthreads();

    uint32_t qh[4][4];
    {
        const uint32_t a_row = lane & 15, a_half = lane >> 4;
        #pragma unroll
        for (int ks = 0; ks < 4; ks++) {
            uint32_t off = (w * 16 + a_row) * AT_RW + (ks * 16 + a_half * 8) * 2;
            ldm_x4(qh[ks], QH + off);
        }
    }

    float o[8][4];
    #pragma unroll
    for (int dt = 0; dt < 8; dt++)
        #pragma unroll
        for (int r = 0; r < 4; r++) o[dt][r] = 0.f;
    float m0 = -1e30f, m1 = -1e30f, l0 = 0.f, l1 = 0.f;

    const int bm = lane >> 3;
    const uint32_t b_sub = (bm >> 1) * 8 + (lane & 7);
    const uint32_t b_khalf = (bm & 1) * 8;
    const uint32_t t_row = lane & 15, t_col = lane >> 4;
    const int rloc = lane >> 2;
    const int cloc = (lane & 3) * 2;

    for (int j = 0; j <= jmax; j++) {
        if (j + 2 <= jmax) {
            attn_load_kv(ST + ((j + 2) % 3) * AT_STAGE, base, j + 2, tid);
            CP_COMMIT();
        }

        const uint32_t KHb = ST + (j % 3) * AT_STAGE;
        const uint32_t VHb = KHb + AT_MAT;

        // ---- S = Q K^T (1 product) ----
        float s[8][4];
        #pragma unroll
        for (int np = 0; np < 4; np++) {
            s[2*np][0]=s[2*np][1]=s[2*np][2]=s[2*np][3]=0.f;
            s[2*np+1][0]=s[2*np+1][1]=s[2*np+1][2]=s[2*np+1][3]=0.f;
            #pragma unroll
            for (int ks = 0; ks < 4; ks++) {
                uint32_t off = (np * 16 + b_sub) * AT_RW + (ks * 16 + b_khalf) * 2;
                uint32_t kh4[4];
                ldm_x4(kh4, KHb + off);
                mma16816(s[2*np],   qh[ks], &kh4[0]);
                mma16816(s[2*np+1], qh[ks], &kh4[2]);
            }
        }

        // ---- causal mask (diagonal tiles) ----
        if (j >= 2 * qb) {
            int r0g = qb * 128 + w * 16 + rloc;
            int c0g = j * 64;
            #pragma unroll
            for (int nt = 0; nt < 8; nt++) {
                int col = c0g + nt * 8 + cloc;
                if (col     > r0g)     s[nt][0] = -1e30f;
                if (col + 1 > r0g)     s[nt][1] = -1e30f;
                if (col     > r0g + 8) s[nt][2] = -1e30f;
                if (col + 1 > r0g + 8) s[nt][3] = -1e30f;
            }
        }

        // ---- online softmax ----
        float mx0 = -1e30f, mx1 = -1e30f;
        #pragma unroll
        for (int nt = 0; nt < 8; nt++) {
            mx0 = fmaxf(mx0, fmaxf(s[nt][0], s[nt][1]));
            mx1 = fmaxf(mx1, fmaxf(s[nt][2], s[nt][3]));
        }
        mx0 = fmaxf(mx0, __shfl_xor_sync(0xffffffffu, mx0, 1));
        mx0 = fmaxf(mx0, __shfl_xor_sync(0xffffffffu, mx0, 2));
        mx1 = fmaxf(mx1, __shfl_xor_sync(0xffffffffu, mx1, 1));
        mx1 = fmaxf(mx1, __shfl_xor_sync(0xffffffffu, mx1, 2));
        float mn0 = fmaxf(m0, mx0), mn1 = fmaxf(m1, mx1);
        float cr0 = __expf(m0 - mn0), cr1 = __expf(m1 - mn1);
        float ls0 = 0.f, ls1 = 0.f;
        #pragma unroll
        for (int nt = 0; nt < 8; nt++) {
            s[nt][0] = __expf(s[nt][0] - mn0); ls0 += s[nt][0];
            s[nt][1] = __expf(s[nt][1] - mn0); ls0 += s[nt][1];
            s[nt][2] = __expf(s[nt][2] - mn1); ls1 += s[nt][2];
            s[nt][3] = __expf(s[nt][3] - mn1); ls1 += s[nt][3];
        }
        ls0 += __shfl_xor_sync(0xffffffffu, ls0, 1);
        ls0 += __shfl_xor_sync(0xffffffffu, ls0, 2);
        ls1 += __shfl_xor_sync(0xffffffffu, ls1, 1);
        ls1 += __shfl_xor_sync(0xffffffffu, ls1, 2);
        l0 = l0 * cr0 + ls0;  m0 = mn0;
        l1 = l1 * cr1 + ls1;  m1 = mn1;
        #pragma unroll
        for (int dt = 0; dt < 8; dt++) {
            o[dt][0] *= cr0; o[dt][1] *= cr0;
            o[dt][2] *= cr1; o[dt][3] *= cr1;
        }

        // ---- P fragments (fp16) ----
        uint32_t ph[4][4];
        #pragma unroll
        for (int kt = 0; kt < 4; kt++) {
            ph[kt][0] = pack2h(s[2*kt][0],   s[2*kt][1]);
            ph[kt][1] = pack2h(s[2*kt][2],   s[2*kt][3]);
            ph[kt][2] = pack2h(s[2*kt+1][0], s[2*kt+1][1]);
            ph[kt][3] = pack2h(s[2*kt+1][2], s[2*kt+1][3]);
        }

        // ---- O += P V (1 product) ----
        #pragma unroll
        for (int dp = 0; dp < 4; dp++) {
            #pragma unroll
            for (int kt = 0; kt < 4; kt++) {
                uint32_t off = (kt * 16 + t_row) * AT_RW + (dp * 2 + t_col) * 16;
                uint32_t vh4[4];
                ldm_x4t(vh4, VHb + off);
                mma16816(o[dp*2],   ph[kt], &vh4[0]);
                mma16816(o[dp*2+1], ph[kt], &vh4[2]);
            }
        }

        if (j < jmax) {
            if (j + 2 <= jmax) { CP_WAIT(1); } else { CP_WAIT(0); }
            __syncthreads();
        }
    }

    // ---- epilogue (fp16 store, concat-head layout) ----
    const float inv0 = 1.f / l0, inv1 = 1.f / l1;
    const int b = bh >> 4, h = bh & 15;
    const int row0 = qb * 128 + w * 16 + rloc;
    #pragma unroll
    for (int dt = 0; dt < 8; dt++) {
        int d = dt * 8 + cloc;
        size_t o0 = ((size_t)(b * TT + row0)) * EE + h * HDD + d;
        size_t o1 = o0 + (size_t)8 * EE;
        *(uint32_t*)(g_a + o0) = pack2h(o[dt][0] * inv0, o[dt][1] * inv0);
        *(uint32_t*)(g_a + o1) = pack2h(o[dt][2] * inv1, o[dt][3] * inv1);
    }
}

// ---------------------------------------------------------------- launch ----
extern "C" void kernel_launch(void* const* d_in, const int* in_sizes, int n_in,
                              void* d_out, int out_size)
{
    const float* x  = (const float*)d_in[0];
    const float* Wq = (const float*)d_in[1];
    const float* Wk = (const float*)d_in[2];
    const float* Wv = (const float*)d_in[3];
    const float* Wo = (const float*)d_in[4];
    const float* bo = (const float*)d_in[5];
    float* out = (float*)d_out;

    const int smem_gemm = 4 * STAGE2;   // 81920
    cudaFuncSetAttribute(gemm_qkv_kernel, cudaFuncAttributeMaxDynamicSharedMemorySize, smem_gemm);
    cudaFuncSetAttribute(gemm_o_kernel,   cudaFuncAttributeMaxDynamicSharedMemorySize, smem_gemm);
    cudaFuncSetAttribute(attn_mma_kernel, cudaFuncAttributeMaxDynamicSharedMemorySize, AT_SMEM);

    conv_x_kernel<<<MM * EE / (256 * 8), 256>>>(x);
    dim3 gw(EE / 32, HDD / 32, HH * 3);
    conv_w_kernel<<<gw, 256>>>(Wq, Wk, Wv);
    conv_wo_kernel<<<EE * EE / 256, 256>>>(Wo);

    dim3 gqkv(MM / 128, EE / 128, 3);
    gemm_qkv_kernel<<<gqkv, 256, smem_gemm>>>();

    dim3 ga(TT / 128, BB * HH);
    attn_mma_kernel<<<ga, 256, AT_SMEM>>>();

    dim3 go(MM / 128, EE / 128);
    gemm_o_kernel<<<go, 256, smem_gemm>>>(bo, out);
}